// round 1
// baseline (speedup 1.0000x reference)
#include <cuda_runtime.h>
#include <math.h>

#define BDIM 2
#define SEQ 2048
#define DMODEL 256
#define SSTATE 16
#define DCONV 4
#define DINNER 512
#define NROWS (BDIM*SEQ)   /* 4096 rows per stream */
#define NSTREAM 3
#define XDBL 48            /* dt(16) + B(16) + C(16) */

// ---------------- scratch (device globals; no allocations allowed) ----------
__device__ __align__(256) float g_xn   [NSTREAM*NROWS*DMODEL];
__device__ __align__(256) float g_xz   [NSTREAM*NROWS*2*DINNER];
__device__ __align__(256) float g_xa   [NSTREAM*NROWS*DINNER];
__device__ __align__(256) float g_xdbl [NSTREAM*NROWS*XDBL];
__device__ __align__(256) float g_dt   [NSTREAM*NROWS*DINNER];
__device__ __align__(256) float g_y    [NSTREAM*NROWS*DINNER];
__device__ __align__(256) float g_multi[NROWS*3*DMODEL];
__device__ __align__(256) float g_pooled[BDIM*3*DMODEL];
__device__ __align__(256) float g_coeffs[BDIM*3];

struct PtrTriple { const float* p[3]; };

// ---------------- layernorm ----------------
__global__ void layernorm_kernel(PtrTriple xs, const float* __restrict__ w,
                                 const float* __restrict__ bb) {
    int row = blockIdx.x;                 // 0 .. 3*4096-1
    int s = row / NROWS;
    int r = row - s * NROWS;
    const float* x = xs.p[s] + (long)r * DMODEL;
    int t = threadIdx.x;                  // 256 threads
    float v = x[t];
    float s1 = v, s2 = v * v;
    #pragma unroll
    for (int o = 16; o; o >>= 1) {
        s1 += __shfl_xor_sync(0xffffffffu, s1, o);
        s2 += __shfl_xor_sync(0xffffffffu, s2, o);
    }
    __shared__ float smA[8], smB[8];
    if ((t & 31) == 0) { smA[t >> 5] = s1; smB[t >> 5] = s2; }
    __syncthreads();
    if (t < 8) {
        float a = smA[t], b = smB[t];
        #pragma unroll
        for (int o = 4; o; o >>= 1) {
            a += __shfl_xor_sync(0xffu, a, o);
            b += __shfl_xor_sync(0xffu, b, o);
        }
        if (t == 0) { smA[0] = a; smB[0] = b; }
    }
    __syncthreads();
    float mean = smA[0] * (1.0f / DMODEL);
    float var  = smB[0] * (1.0f / DMODEL) - mean * mean;
    float inv  = rsqrtf(var + 1e-5f);
    g_xn[(long)row * DMODEL + t] = (v - mean) * inv * w[s * DMODEL + t] + bb[s * DMODEL + t];
}

// ---------------- generic tiled GEMM: C = A(MxK) * B(NxK)^T ----------------
// MODE 0: plain       MODE 1: softplus(acc + bias[col])
// MODE 2: acc + addTri.p[z][row*ldadd+col], stored at C[row*ldc + col + z*cColOff]
// MODE 3: acc + bias[col] + sum_s coeffs[b][s]*addTri.p[0][row*ldadd + s*256 + col]
template<int BM, int BN, int BK, int TM, int TN, int MODE>
__global__ void __launch_bounds__((BM/TM)*(BN/TN))
gemm_abt(const float* __restrict__ A, long aB, int lda,
         const float* __restrict__ B, long bB, int ldb,
         float* __restrict__ C, long cB, int ldc, int cColOff,
         int M, int N, int K,
         const float* __restrict__ bias, long biasB,
         PtrTriple addTri, int ldadd,
         const float* __restrict__ coeffs, int seqN)
{
    constexpr int THREADS = (BM/TM)*(BN/TN);
    __shared__ float As[BK][BM + 4];
    __shared__ float Bs[BK][BN + 4];
    int z = blockIdx.z;
    const float* Ab = A + (long)z * aB + (long)blockIdx.y * BM * lda;
    const float* Bb = B + (long)z * bB + (long)blockIdx.x * BN * ldb;
    int t  = threadIdx.x;
    int tn = t % (BN / TN);
    int tm = t / (BN / TN);
    float acc[TM][TN];
    #pragma unroll
    for (int i = 0; i < TM; i++)
        #pragma unroll
        for (int j = 0; j < TN; j++) acc[i][j] = 0.f;

    for (int k0 = 0; k0 < K; k0 += BK) {
        for (int i = t * 4; i < BM * BK; i += THREADS * 4) {
            int r = i / BK, c = i % BK;
            float4 v = *(const float4*)(Ab + (long)r * lda + k0 + c);
            As[c + 0][r] = v.x; As[c + 1][r] = v.y;
            As[c + 2][r] = v.z; As[c + 3][r] = v.w;
        }
        for (int i = t * 4; i < BN * BK; i += THREADS * 4) {
            int r = i / BK, c = i % BK;
            float4 v = *(const float4*)(Bb + (long)r * ldb + k0 + c);
            Bs[c + 0][r] = v.x; Bs[c + 1][r] = v.y;
            Bs[c + 2][r] = v.z; Bs[c + 3][r] = v.w;
        }
        __syncthreads();
        #pragma unroll
        for (int k = 0; k < BK; k++) {
            float am[TM], bn[TN];
            #pragma unroll
            for (int i = 0; i < TM; i++) am[i] = As[k][tm * TM + i];
            #pragma unroll
            for (int j = 0; j < TN; j++) bn[j] = Bs[k][tn * TN + j];
            #pragma unroll
            for (int i = 0; i < TM; i++)
                #pragma unroll
                for (int j = 0; j < TN; j++)
                    acc[i][j] += am[i] * bn[j];
        }
        __syncthreads();
    }

    int row0 = blockIdx.y * BM + tm * TM;
    int col0 = blockIdx.x * BN + tn * TN;

    #pragma unroll
    for (int i = 0; i < TM; i++) {
        int row = row0 + i;
        #pragma unroll
        for (int j = 0; j < TN; j++) {
            int col = col0 + j;
            float v = acc[i][j];
            if (MODE == 0) {
                (C + (long)z * cB)[(long)row * ldc + col] = v;
            } else if (MODE == 1) {
                float x = v + bias[z * biasB + col];
                (C + (long)z * cB)[(long)row * ldc + col] =
                    fmaxf(x, 0.f) + log1pf(expf(-fabsf(x)));
            } else if (MODE == 2) {
                const float* ad = addTri.p[z];
                C[(long)row * ldc + col + z * cColOff] =
                    v + ad[(long)row * ldadd + col];
            } else { // MODE 3
                int bidx = row / seqN;
                float c0 = coeffs[bidx * 3 + 0];
                float c1 = coeffs[bidx * 3 + 1];
                float c2 = coeffs[bidx * 3 + 2];
                const float* mrow = addTri.p[0] + (long)row * ldadd;
                C[(long)row * ldc + col] = v + bias[col]
                    + c0 * mrow[col] + c1 * mrow[col + 256] + c2 * mrow[col + 512];
            }
        }
    }
}

// ---------------- causal depthwise conv (DC=4) + SiLU ----------------
__global__ void conv_silu_kernel(const float* __restrict__ conv_w,
                                 const float* __restrict__ conv_b) {
    int idx = blockIdx.x * blockDim.x + threadIdx.x;
    if (idx >= NSTREAM * NROWS * DINNER) return;
    int d    = idx % DINNER;
    int rest = idx / DINNER;
    int n    = rest % SEQ;
    int sb   = rest / SEQ;        // stream*B + b, 0..5
    int si   = sb / BDIM;
    const float* base = g_xz + (long)sb * SEQ * (2 * DINNER) + d;
    const float* cw   = conv_w + (si * DINNER + d) * DCONV;
    float acc = conv_b[si * DINNER + d];
    #pragma unroll
    for (int k = 0; k < DCONV; k++) {
        int m = n + k - (DCONV - 1);
        if (m >= 0) acc += base[(long)m * (2 * DINNER)] * cw[k];
    }
    g_xa[idx] = acc / (1.f + expf(-acc));
}

// ---------------- selective scan: half-warp per (stream,b,channel) ----------
__global__ void scan_kernel(const float* __restrict__ A_log,
                            const float* __restrict__ Dp) {
    int warp = (blockIdx.x * blockDim.x + threadIdx.x) >> 5;
    int lane = threadIdx.x & 31;
    int half = lane >> 4;
    int sl   = lane & 15;                 // state index
    int u    = warp * 2 + half;           // 0..3071
    int si   = u / (BDIM * DINNER);
    int rem  = u - si * BDIM * DINNER;
    int b    = rem / DINNER;
    int d    = rem - b * DINNER;
    long sb  = (long)si * BDIM + b;

    const float* dt = g_dt + sb * SEQ * DINNER + d;
    const float* xa = g_xa + sb * SEQ * DINNER + d;
    const float* zz = g_xz + sb * SEQ * (2 * DINNER) + DINNER + d;
    const float* xd = g_xdbl + sb * SEQ * XDBL;
    float a   = -expf(A_log[(si * DINNER + d) * SSTATE + sl]);
    float Dpd = Dp[si * DINNER + d];
    float* yo = g_y + sb * SEQ * DINNER + d;

    float h = 0.f;
    for (int n = 0; n < SEQ; n++) {
        float dtv = dt[(long)n * DINNER];
        float xav = xa[(long)n * DINNER];
        float Bv  = xd[n * XDBL + 16 + sl];
        float Cv  = xd[n * XDBL + 32 + sl];
        h = expf(dtv * a) * h + dtv * Bv * xav;
        float p = h * Cv;
        p += __shfl_xor_sync(0xffffffffu, p, 8);
        p += __shfl_xor_sync(0xffffffffu, p, 4);
        p += __shfl_xor_sync(0xffffffffu, p, 2);
        p += __shfl_xor_sync(0xffffffffu, p, 1);
        if (sl == 0) {
            float zv = zz[(long)n * (2 * DINNER)];
            float sz = zv / (1.f + expf(-zv));
            yo[(long)n * DINNER] = (p + xav * Dpd) * sz;
        }
    }
}

// ---------------- mean pool over sequence ----------------
__global__ void pool_kernel() {
    int b = blockIdx.x;
    int j = threadIdx.x;                  // 768 threads
    const float* base = g_multi + (long)b * SEQ * 768 + j;
    float s = 0.f;
    for (int n = 0; n < SEQ; n++) s += base[(long)n * 768];
    g_pooled[b * 768 + j] = s * (1.f / SEQ);
}

// ---------------- aggregation coefficients ----------------
__global__ void coeffs_kernel(const float* __restrict__ w1, const float* __restrict__ b1,
                              const float* __restrict__ w2, const float* __restrict__ b2,
                              const float* __restrict__ temp) {
    int b = blockIdx.x;
    int d = threadIdx.x;                  // 256 threads
    const float* p = g_pooled + b * 768;
    const float* wr = w1 + (long)d * 768;
    float acc = b1[d];
    for (int e = 0; e < 768; e++) acc += p[e] * wr[e];
    // tanh-approx GELU (jax default approximate=True)
    float x = acc;
    float cc = 0.7978845608028654f * (x + 0.044715f * x * x * x);
    float hg = 0.5f * x * (1.f + tanhf(cc));

    __shared__ float red[256];
    float logits[3];
    for (int k = 0; k < 3; k++) {
        red[d] = hg * w2[k * 256 + d];
        __syncthreads();
        for (int o = 128; o; o >>= 1) {
            if (d < o) red[d] += red[d + o];
            __syncthreads();
        }
        logits[k] = red[0] + b2[k];
        __syncthreads();
    }
    if (d == 0) {
        float m = fmaxf(logits[0], fmaxf(logits[1], logits[2]));
        float e0 = expf(logits[0] - m), e1 = expf(logits[1] - m), e2 = expf(logits[2] - m);
        float s = e0 + e1 + e2; e0 /= s; e1 /= s; e2 /= s;
        float invt = 1.f / (temp[0] + 1e-6f);
        float mm = fmaxf(e0, fmaxf(e1, e2)) * invt;
        float f0 = expf(e0 * invt - mm), f1 = expf(e1 * invt - mm), f2 = expf(e2 * invt - mm);
        float ss = f0 + f1 + f2;
        g_coeffs[b * 3 + 0] = f0 / ss;
        g_coeffs[b * 3 + 1] = f1 / ss;
        g_coeffs[b * 3 + 2] = f2 / ss;
    }
}

// ---------------- launch ----------------
extern "C" void kernel_launch(void* const* d_in, const int* in_sizes, int n_in,
                              void* d_out, int out_size) {
    const float* edge    = (const float*)d_in[0];
    const float* blob    = (const float*)d_in[1];
    const float* spec    = (const float*)d_in[2];
    const float* norm_w  = (const float*)d_in[3];
    const float* norm_b  = (const float*)d_in[4];
    const float* in_w    = (const float*)d_in[5];
    const float* conv_w  = (const float*)d_in[6];
    const float* conv_b  = (const float*)d_in[7];
    const float* xproj_w = (const float*)d_in[8];
    const float* dt_w    = (const float*)d_in[9];
    const float* dt_b    = (const float*)d_in[10];
    const float* A_log   = (const float*)d_in[11];
    const float* Dp      = (const float*)d_in[12];
    const float* out_w   = (const float*)d_in[13];
    const float* temp    = (const float*)d_in[14];
    const float* agg_w1  = (const float*)d_in[15];
    const float* agg_b1  = (const float*)d_in[16];
    const float* agg_w2  = (const float*)d_in[17];
    const float* agg_b2  = (const float*)d_in[18];
    const float* proj_w  = (const float*)d_in[19];
    const float* proj_b  = (const float*)d_in[20];
    float* out = (float*)d_out;

    float *xn, *xz, *xa, *xdbl, *dtb, *yb, *multi, *coef;
    cudaGetSymbolAddress((void**)&xn,    g_xn);
    cudaGetSymbolAddress((void**)&xz,    g_xz);
    cudaGetSymbolAddress((void**)&xa,    g_xa);
    cudaGetSymbolAddress((void**)&xdbl,  g_xdbl);
    cudaGetSymbolAddress((void**)&dtb,   g_dt);
    cudaGetSymbolAddress((void**)&yb,    g_y);
    cudaGetSymbolAddress((void**)&multi, g_multi);
    cudaGetSymbolAddress((void**)&coef,  g_coeffs);

    PtrTriple tri;  tri.p[0] = edge; tri.p[1] = blob; tri.p[2] = spec;
    PtrTriple tri0; tri0.p[0] = nullptr; tri0.p[1] = nullptr; tri0.p[2] = nullptr;
    PtrTriple triM; triM.p[0] = multi; triM.p[1] = nullptr; triM.p[2] = nullptr;

    // 1) layernorm
    layernorm_kernel<<<NSTREAM * NROWS, 256>>>(tri, norm_w, norm_b);

    // 2) in_proj: xz = xn @ in_w^T   (M=4096,N=1024,K=256 per stream)
    gemm_abt<64,64,16,4,4,0><<<dim3(1024/64, NROWS/64, 3), 256>>>(
        xn, (long)NROWS*DMODEL, DMODEL,
        in_w, (long)1024*DMODEL, DMODEL,
        xz, (long)NROWS*1024, 1024, 0,
        NROWS, 1024, DMODEL, nullptr, 0, tri0, 0, nullptr, 0);

    // 3) conv + silu
    conv_silu_kernel<<<(NSTREAM*NROWS*DINNER)/256, 256>>>(conv_w, conv_b);

    // 4) xproj: x_dbl = xa @ xproj_w^T (M=4096,N=48,K=512)
    gemm_abt<64,48,16,4,3,0><<<dim3(1, NROWS/64, 3), 256>>>(
        xa, (long)NROWS*DINNER, DINNER,
        xproj_w, (long)XDBL*DINNER, DINNER,
        xdbl, (long)NROWS*XDBL, XDBL, 0,
        NROWS, XDBL, DINNER, nullptr, 0, tri0, 0, nullptr, 0);

    // 5) dt = softplus(x_dbl[:, :16] @ dt_w^T + dt_b)  (M=4096,N=512,K=16)
    gemm_abt<64,64,16,4,4,1><<<dim3(512/64, NROWS/64, 3), 256>>>(
        xdbl, (long)NROWS*XDBL, XDBL,
        dt_w, (long)DINNER*16, 16,
        dtb, (long)NROWS*DINNER, DINNER, 0,
        NROWS, DINNER, 16, dt_b, DINNER, tri0, 0, nullptr, 0);

    // 6) selective scan (+ D skip + silu(z) gate)
    scan_kernel<<<192, 256>>>(A_log, Dp);

    // 7) out_proj + residual, stored into concat layout multi (B,N,3*256)
    gemm_abt<64,64,16,4,4,2><<<dim3(DMODEL/64, NROWS/64, 3), 256>>>(
        yb, (long)NROWS*DINNER, DINNER,
        out_w, (long)DMODEL*DINNER, DINNER,
        multi, 0, 3*DMODEL, DMODEL,
        NROWS, DMODEL, DINNER, nullptr, 0, tri, DMODEL, nullptr, 0);

    // 8) mean pool over N
    pool_kernel<<<BDIM, 768>>>();

    // 9) aggregation coefficients (gelu -> double softmax)
    coeffs_kernel<<<BDIM, 256>>>(agg_w1, agg_b1, agg_w2, agg_b2, temp);

    // 10) final: out = multi @ proj_w^T + proj_b + coeff-weighted streams
    gemm_abt<64,64,16,4,4,3><<<dim3(DMODEL/64, NROWS/64, 1), 256>>>(
        multi, 0, 3*DMODEL,
        proj_w, 0, 3*DMODEL,
        out, 0, DMODEL, 0,
        NROWS, DMODEL, 3*DMODEL, proj_b, 0, triM, 3*DMODEL, coef, SEQ);
}

// round 2
// speedup vs baseline: 2.1869x; 2.1869x over previous
#include <cuda_runtime.h>
#include <math.h>

#define BDIM 2
#define SEQ 2048
#define DMODEL 256
#define SSTATE 16
#define DCONV 4
#define DINNER 512
#define NROWS (BDIM*SEQ)   /* 4096 rows per stream */
#define NSTREAM 3
#define XDBL 48            /* dt(16) + B(16) + C(16) */
#define NC 16              /* scan chunks */
#define TCH (SEQ/NC)       /* 128 steps per chunk */

// ---------------- scratch (device globals; no allocations allowed) ----------
__device__ __align__(256) float g_xn   [NSTREAM*NROWS*DMODEL];
__device__ __align__(256) float g_xz   [NSTREAM*NROWS*2*DINNER];
__device__ __align__(256) float g_xa   [NSTREAM*NROWS*DINNER];
__device__ __align__(256) float g_xdbl [NSTREAM*NROWS*XDBL];
__device__ __align__(256) float g_dt   [NSTREAM*NROWS*DINNER];
__device__ __align__(256) float g_y    [NSTREAM*NROWS*DINNER];
__device__ __align__(256) float g_multi[NROWS*3*DMODEL];
__device__ __align__(256) float g_poolpart[BDIM*NC*3*DMODEL];
__device__ __align__(256) float g_pooled[BDIM*3*DMODEL];
__device__ __align__(256) float g_coeffs[BDIM*3];

struct PtrTriple { const float* p[3]; };

// ---------------- layernorm ----------------
__global__ void layernorm_kernel(PtrTriple xs, const float* __restrict__ w,
                                 const float* __restrict__ bb) {
    int row = blockIdx.x;                 // 0 .. 3*4096-1
    int s = row / NROWS;
    int r = row - s * NROWS;
    const float* x = xs.p[s] + (long)r * DMODEL;
    int t = threadIdx.x;                  // 256 threads
    float v = x[t];
    float s1 = v, s2 = v * v;
    #pragma unroll
    for (int o = 16; o; o >>= 1) {
        s1 += __shfl_xor_sync(0xffffffffu, s1, o);
        s2 += __shfl_xor_sync(0xffffffffu, s2, o);
    }
    __shared__ float smA[8], smB[8];
    if ((t & 31) == 0) { smA[t >> 5] = s1; smB[t >> 5] = s2; }
    __syncthreads();
    if (t < 8) {
        float a = smA[t], b = smB[t];
        #pragma unroll
        for (int o = 4; o; o >>= 1) {
            a += __shfl_xor_sync(0xffu, a, o);
            b += __shfl_xor_sync(0xffu, b, o);
        }
        if (t == 0) { smA[0] = a; smB[0] = b; }
    }
    __syncthreads();
    float mean = smA[0] * (1.0f / DMODEL);
    float var  = smB[0] * (1.0f / DMODEL) - mean * mean;
    float inv  = rsqrtf(var + 1e-5f);
    g_xn[(long)row * DMODEL + t] = (v - mean) * inv * w[s * DMODEL + t] + bb[s * DMODEL + t];
}

// ---------------- tiled GEMM v2: C = A(MxK) * B(NxK)^T ----------------
// MODE 0: plain       MODE 1: softplus(acc + bias[z][col])
// MODE 2: acc + addTri.p[z][row*ldadd+col] stored at C[row*ldc+col+z*cColOff]
// MODE 3: acc + bias[col] + sum_s coeffs[b][s]*addTri.p[0][row*ldadd + s*256 + col]
template<int BM, int BN, int BK, int TM, int TN, int MODE>
__global__ void __launch_bounds__((BM/TM)*(BN/TN))
gemm2(const float* __restrict__ A, long aB, int lda,
      const float* __restrict__ B, long bB, int ldb,
      float* __restrict__ C, long cB, int ldc, int cColOff,
      int M, int N, int K,
      const float* __restrict__ bias, long biasB,
      PtrTriple addTri, int ldadd,
      const float* __restrict__ coeffs, int seqN)
{
    constexpr int THREADS = (BM/TM)*(BN/TN);
    __shared__ float As[BK][BM + 4];
    __shared__ float Bs[BK][BN + 4];
    int z = blockIdx.z;
    const float* Ab = A + (long)z * aB + (long)blockIdx.y * BM * lda;
    const float* Bb = B + (long)z * bB + (long)blockIdx.x * BN * ldb;
    int bRow0 = blockIdx.x * BN;
    int t  = threadIdx.x;
    int tn = t % (BN / TN);
    int tm = t / (BN / TN);

    float acc[TM][TN];
    #pragma unroll
    for (int i = 0; i < TM; i++)
        #pragma unroll
        for (int j = 0; j < TN; j++) acc[i][j] = 0.f;

    float4 ra, rb;
    bool aAct = (t * 4 < BM * BK);
    bool bAct = (t * 4 < BN * BK);
    int aR = (t * 4) / BK, aC = (t * 4) % BK;
    int bR = (t * 4) / BK, bC = (t * 4) % BK;

    // prefetch tile 0
    if (aAct) ra = *(const float4*)(Ab + (long)aR * lda + aC);
    if (bAct) {
        if (bRow0 + bR < N) rb = *(const float4*)(Bb + (long)bR * ldb + bC);
        else rb = make_float4(0.f, 0.f, 0.f, 0.f);
    }

    for (int k0 = 0; k0 < K; k0 += BK) {
        if (aAct) {
            As[aC + 0][aR] = ra.x; As[aC + 1][aR] = ra.y;
            As[aC + 2][aR] = ra.z; As[aC + 3][aR] = ra.w;
        }
        if (bAct) {
            Bs[bC + 0][bR] = rb.x; Bs[bC + 1][bR] = rb.y;
            Bs[bC + 2][bR] = rb.z; Bs[bC + 3][bR] = rb.w;
        }
        __syncthreads();
        int kn = k0 + BK;
        if (kn < K) {
            if (aAct) ra = *(const float4*)(Ab + (long)aR * lda + kn + aC);
            if (bAct) {
                if (bRow0 + bR < N) rb = *(const float4*)(Bb + (long)bR * ldb + kn + bC);
                else rb = make_float4(0.f, 0.f, 0.f, 0.f);
            }
        }
        #pragma unroll
        for (int k = 0; k < BK; k++) {
            float am[TM], bn[TN];
            #pragma unroll
            for (int i = 0; i < TM; i += 4)
                *(float4*)&am[i] = *(const float4*)&As[k][tm * TM + i];
            #pragma unroll
            for (int j = 0; j < TN; j += 4)
                *(float4*)&bn[j] = *(const float4*)&Bs[k][tn * TN + j];
            #pragma unroll
            for (int i = 0; i < TM; i++)
                #pragma unroll
                for (int j = 0; j < TN; j++)
                    acc[i][j] = fmaf(am[i], bn[j], acc[i][j]);
        }
        __syncthreads();
    }

    int row0 = blockIdx.y * BM + tm * TM;
    int col0 = blockIdx.x * BN + tn * TN;

    #pragma unroll
    for (int i = 0; i < TM; i++) {
        int row = row0 + i;
        #pragma unroll
        for (int j = 0; j < TN; j++) {
            int col = col0 + j;
            if (col >= N) continue;
            float v = acc[i][j];
            if (MODE == 0) {
                (C + (long)z * cB)[(long)row * ldc + col] = v;
            } else if (MODE == 1) {
                float x = v + bias[z * biasB + col];
                (C + (long)z * cB)[(long)row * ldc + col] =
                    fmaxf(x, 0.f) + log1pf(expf(-fabsf(x)));
            } else if (MODE == 2) {
                const float* ad = addTri.p[z];
                C[(long)row * ldc + col + z * cColOff] =
                    v + ad[(long)row * ldadd + col];
            } else { // MODE 3
                int bidx = row / seqN;
                float c0 = coeffs[bidx * 3 + 0];
                float c1 = coeffs[bidx * 3 + 1];
                float c2 = coeffs[bidx * 3 + 2];
                const float* mrow = addTri.p[0] + (long)row * ldadd;
                C[(long)row * ldc + col] = v + bias[col]
                    + c0 * mrow[col] + c1 * mrow[col + 256] + c2 * mrow[col + 512];
            }
        }
    }
}

// ---------------- causal depthwise conv (DC=4) + SiLU ----------------
__global__ void conv_silu_kernel(const float* __restrict__ conv_w,
                                 const float* __restrict__ conv_b) {
    int idx = blockIdx.x * blockDim.x + threadIdx.x;
    if (idx >= NSTREAM * NROWS * DINNER) return;
    int d    = idx % DINNER;
    int rest = idx / DINNER;
    int n    = rest % SEQ;
    int sb   = rest / SEQ;        // stream*B + b, 0..5
    int si   = sb / BDIM;
    const float* base = g_xz + (long)sb * SEQ * (2 * DINNER) + d;
    const float* cw   = conv_w + (si * DINNER + d) * DCONV;
    float acc = conv_b[si * DINNER + d];
    #pragma unroll
    for (int k = 0; k < DCONV; k++) {
        int m = n + k - (DCONV - 1);
        if (m >= 0) acc = fmaf(base[(long)m * (2 * DINNER)], cw[k], acc);
    }
    g_xa[idx] = acc / (1.f + __expf(-acc));
}

// ------- chunked selective scan: block = 1 channel, 16 chunks x 16 states ---
__global__ void __launch_bounds__(NC*SSTATE)
scan_kernel(const float* __restrict__ A_log, const float* __restrict__ Dp) {
    int ch = blockIdx.x;                    // 0..3071 = (stream, b, d)
    int si = ch / (BDIM * DINNER);
    int rem = ch - si * (BDIM * DINNER);
    int b = rem / DINNER;
    int d = rem - b * DINNER;
    int t = threadIdx.x;
    int chunk = t >> 4;
    int sl = t & 15;
    long sb = (long)si * BDIM + b;

    const float* dt = g_dt + sb * SEQ * DINNER + d;
    const float* xa = g_xa + sb * SEQ * DINNER + d;
    const float* xd = g_xdbl + sb * SEQ * XDBL;
    float a = -__expf(A_log[(si * DINNER + d) * SSTATE + sl]);

    int n0 = chunk * TCH;

    // phase 1: local scan with h0=0, plus decay-product via sum of dt
    float h = 0.f, sdt = 0.f;
    #pragma unroll 2
    for (int n = n0; n < n0 + TCH; n++) {
        float dtv = dt[(long)n * DINNER];
        float xav = xa[(long)n * DINNER];
        float Bv  = xd[n * XDBL + 16 + sl];
        float e = __expf(dtv * a);
        h = fmaf(e, h, (dtv * Bv) * xav);
        sdt += dtv;
    }

    __shared__ float sP[NC][SSTATE], sL[NC][SSTATE], sH[NC][SSTATE];
    sP[chunk][sl] = __expf(a * sdt);
    sL[chunk][sl] = h;
    __syncthreads();

    // combine: initial state for each chunk (16 threads, one per state)
    if (t < SSTATE) {
        float H = 0.f;
        #pragma unroll
        for (int c = 0; c < NC; c++) {
            sH[c][t] = H;
            H = fmaf(sP[c][t], H, sL[c][t]);
        }
    }
    __syncthreads();

    // phase 2: rescan with correct init, emit y
    float hh = sH[chunk][sl];
    float Dpd = Dp[si * DINNER + d];
    const float* zz = g_xz + sb * SEQ * (2 * DINNER) + DINNER + d;
    float* yo = g_y + sb * SEQ * DINNER + d;
    #pragma unroll 2
    for (int n = n0; n < n0 + TCH; n++) {
        float dtv = dt[(long)n * DINNER];
        float xav = xa[(long)n * DINNER];
        float Bv  = xd[n * XDBL + 16 + sl];
        float Cv  = xd[n * XDBL + 32 + sl];
        float e = __expf(dtv * a);
        hh = fmaf(e, hh, (dtv * Bv) * xav);
        float p = hh * Cv;
        p += __shfl_xor_sync(0xffffffffu, p, 8);
        p += __shfl_xor_sync(0xffffffffu, p, 4);
        p += __shfl_xor_sync(0xffffffffu, p, 2);
        p += __shfl_xor_sync(0xffffffffu, p, 1);
        if (sl == 0) {
            float zv = zz[(long)n * (2 * DINNER)];
            float sz = zv / (1.f + __expf(-zv));
            yo[(long)n * DINNER] = (p + xav * Dpd) * sz;
        }
    }
}

// ---------------- mean pool over sequence (two stages) ----------------
__global__ void pool1_kernel() {
    int c = blockIdx.x;                   // chunk 0..15
    int b = blockIdx.y;
    int j = threadIdx.x;                  // 768 threads
    const float* base = g_multi + ((long)b * SEQ + c * (SEQ / NC)) * 768 + j;
    float s = 0.f;
    #pragma unroll 4
    for (int n = 0; n < SEQ / NC; n++) s += base[(long)n * 768];
    g_poolpart[((long)b * NC + c) * 768 + j] = s;
}
__global__ void pool2_kernel() {
    int b = blockIdx.x;
    int j = threadIdx.x;
    float s = 0.f;
    #pragma unroll
    for (int c = 0; c < NC; c++) s += g_poolpart[((long)b * NC + c) * 768 + j];
    g_pooled[b * 768 + j] = s * (1.f / SEQ);
}

// ---------------- aggregation coefficients ----------------
__global__ void coeffs_kernel(const float* __restrict__ w1, const float* __restrict__ b1,
                              const float* __restrict__ w2, const float* __restrict__ b2,
                              const float* __restrict__ temp) {
    int b = blockIdx.x;
    int d = threadIdx.x;                  // 256 threads
    const float* p = g_pooled + b * 768;
    const float* wr = w1 + (long)d * 768;
    float acc = b1[d];
    for (int e = 0; e < 768; e++) acc = fmaf(p[e], wr[e], acc);
    // tanh-approx GELU (jax default approximate=True)
    float x = acc;
    float cc = 0.7978845608028654f * (x + 0.044715f * x * x * x);
    float hg = 0.5f * x * (1.f + tanhf(cc));

    __shared__ float red[256];
    float logits[3];
    for (int k = 0; k < 3; k++) {
        red[d] = hg * w2[k * 256 + d];
        __syncthreads();
        for (int o = 128; o; o >>= 1) {
            if (d < o) red[d] += red[d + o];
            __syncthreads();
        }
        logits[k] = red[0] + b2[k];
        __syncthreads();
    }
    if (d == 0) {
        float m = fmaxf(logits[0], fmaxf(logits[1], logits[2]));
        float e0 = expf(logits[0] - m), e1 = expf(logits[1] - m), e2 = expf(logits[2] - m);
        float s = e0 + e1 + e2; e0 /= s; e1 /= s; e2 /= s;
        float invt = 1.f / (temp[0] + 1e-6f);
        float mm = fmaxf(e0, fmaxf(e1, e2)) * invt;
        float f0 = expf(e0 * invt - mm), f1 = expf(e1 * invt - mm), f2 = expf(e2 * invt - mm);
        float ss = f0 + f1 + f2;
        g_coeffs[b * 3 + 0] = f0 / ss;
        g_coeffs[b * 3 + 1] = f1 / ss;
        g_coeffs[b * 3 + 2] = f2 / ss;
    }
}

// ---------------- launch ----------------
extern "C" void kernel_launch(void* const* d_in, const int* in_sizes, int n_in,
                              void* d_out, int out_size) {
    const float* edge    = (const float*)d_in[0];
    const float* blob    = (const float*)d_in[1];
    const float* spec    = (const float*)d_in[2];
    const float* norm_w  = (const float*)d_in[3];
    const float* norm_b  = (const float*)d_in[4];
    const float* in_w    = (const float*)d_in[5];
    const float* conv_w  = (const float*)d_in[6];
    const float* conv_b  = (const float*)d_in[7];
    const float* xproj_w = (const float*)d_in[8];
    const float* dt_w    = (const float*)d_in[9];
    const float* dt_b    = (const float*)d_in[10];
    const float* A_log   = (const float*)d_in[11];
    const float* Dp      = (const float*)d_in[12];
    const float* out_w   = (const float*)d_in[13];
    const float* temp    = (const float*)d_in[14];
    const float* agg_w1  = (const float*)d_in[15];
    const float* agg_b1  = (const float*)d_in[16];
    const float* agg_w2  = (const float*)d_in[17];
    const float* agg_b2  = (const float*)d_in[18];
    const float* proj_w  = (const float*)d_in[19];
    const float* proj_b  = (const float*)d_in[20];
    float* out = (float*)d_out;

    float *xn, *xz, *xa, *xdbl, *dtb, *yb, *multi, *coef;
    cudaGetSymbolAddress((void**)&xn,    g_xn);
    cudaGetSymbolAddress((void**)&xz,    g_xz);
    cudaGetSymbolAddress((void**)&xa,    g_xa);
    cudaGetSymbolAddress((void**)&xdbl,  g_xdbl);
    cudaGetSymbolAddress((void**)&dtb,   g_dt);
    cudaGetSymbolAddress((void**)&yb,    g_y);
    cudaGetSymbolAddress((void**)&multi, g_multi);
    cudaGetSymbolAddress((void**)&coef,  g_coeffs);

    PtrTriple tri;  tri.p[0] = edge; tri.p[1] = blob; tri.p[2] = spec;
    PtrTriple tri0; tri0.p[0] = nullptr; tri0.p[1] = nullptr; tri0.p[2] = nullptr;
    PtrTriple triM; triM.p[0] = multi; triM.p[1] = nullptr; triM.p[2] = nullptr;

    // 1) layernorm
    layernorm_kernel<<<NSTREAM * NROWS, 256>>>(tri, norm_w, norm_b);

    // 2) in_proj: xz = xn @ in_w^T   (M=4096, N=1024, K=256 per stream)
    gemm2<128,128,8,8,8,0><<<dim3(1024/128, NROWS/128, 3), 256>>>(
        xn, (long)NROWS*DMODEL, DMODEL,
        in_w, (long)1024*DMODEL, DMODEL,
        xz, (long)NROWS*1024, 1024, 0,
        NROWS, 1024, DMODEL, nullptr, 0, tri0, 0, nullptr, 0);

    // 3) conv + silu
    conv_silu_kernel<<<(NSTREAM*NROWS*DINNER)/256, 256>>>(conv_w, conv_b);

    // 4) xproj: x_dbl = xa @ xproj_w^T (M=4096, N=48, K=512)
    gemm2<128,64,8,8,4,0><<<dim3(1, NROWS/128, 3), 256>>>(
        xa, (long)NROWS*DINNER, DINNER,
        xproj_w, (long)XDBL*DINNER, DINNER,
        xdbl, (long)NROWS*XDBL, XDBL, 0,
        NROWS, XDBL, DINNER, nullptr, 0, tri0, 0, nullptr, 0);

    // 5) dt = softplus(x_dbl[:, :16] @ dt_w^T + dt_b)  (M=4096, N=512, K=16)
    gemm2<128,128,8,8,8,1><<<dim3(512/128, NROWS/128, 3), 256>>>(
        xdbl, (long)NROWS*XDBL, XDBL,
        dt_w, (long)DINNER*16, 16,
        dtb, (long)NROWS*DINNER, DINNER, 0,
        NROWS, DINNER, 16, dt_b, DINNER, tri0, 0, nullptr, 0);

    // 6) chunked selective scan (+ D skip + silu(z) gate)
    scan_kernel<<<NSTREAM*BDIM*DINNER, NC*SSTATE>>>(A_log, Dp);

    // 7) out_proj + residual, stored into concat layout multi (B,N,3*256)
    gemm2<128,128,8,8,8,2><<<dim3(DMODEL/128, NROWS/128, 3), 256>>>(
        yb, (long)NROWS*DINNER, DINNER,
        out_w, (long)DMODEL*DINNER, DINNER,
        multi, 0, 3*DMODEL, DMODEL,
        NROWS, DMODEL, DINNER, nullptr, 0, tri, DMODEL, nullptr, 0);

    // 8) mean pool over N (two stage)
    pool1_kernel<<<dim3(NC, BDIM), 768>>>();
    pool2_kernel<<<BDIM, 768>>>();

    // 9) aggregation coefficients (gelu -> double softmax)
    coeffs_kernel<<<BDIM, 256>>>(agg_w1, agg_b1, agg_w2, agg_b2, temp);

    // 10) final: out = multi @ proj_w^T + proj_b + coeff-weighted streams
    gemm2<128,64,8,8,4,3><<<dim3(DMODEL/64, NROWS/128, 1), 256>>>(
        multi, 0, 3*DMODEL,
        proj_w, 0, 3*DMODEL,
        out, 0, DMODEL, 0,
        NROWS, DMODEL, 3*DMODEL, proj_b, 0, triM, 3*DMODEL, coef, SEQ);
}

// round 4
// speedup vs baseline: 2.5702x; 1.1753x over previous
#include <cuda_runtime.h>
#include <cstdint>
#include <math.h>

#define BDIM 2
#define SEQ 2048
#define DMODEL 256
#define SSTATE 16
#define DCONV 4
#define DINNER 512
#define NROWS (BDIM*SEQ)   /* 4096 rows per stream */
#define NSTREAM 3
#define XDBL 48            /* dt(16) + B(16) + C(16) */
#define NC 16              /* scan chunks */
#define TCH (SEQ/NC)       /* 128 steps per chunk */

// tcgen05 is an arch-SPECIFIC (sm_103a / sm_103f) feature. Some compile passes
// target plain compute_103, where ptxas rejects it. Compile the tensor body only
// when the feature is available; otherwise compile a SIMT fallback body for the
// SAME kernel symbol. The runtime loads whichever cubin matches.
#if defined(__CUDA_ARCH_FEAT_SM103_ALL) \
 || (defined(__CUDA_ARCH_SPECIFIC__) && (__CUDA_ARCH_SPECIFIC__ == 1030)) \
 || (defined(__CUDA_ARCH_FAMILY_SPECIFIC__) && (__CUDA_ARCH_FAMILY_SPECIFIC__ == 1030))
#define HAS_TC 1
#else
#define HAS_TC 0
#endif

// ---------------- scratch (device globals; no allocations allowed) ----------
__device__ __align__(256) float g_xn   [NSTREAM*NROWS*DMODEL];
__device__ __align__(256) float g_xz   [NSTREAM*NROWS*2*DINNER];
__device__ __align__(256) float g_xa   [NSTREAM*NROWS*DINNER];
__device__ __align__(256) float g_xdbl [NSTREAM*NROWS*XDBL];
__device__ __align__(256) float g_dt   [NSTREAM*NROWS*DINNER];
__device__ __align__(256) float g_y    [NSTREAM*NROWS*DINNER];
__device__ __align__(256) float g_multi[NROWS*3*DMODEL];
__device__ __align__(256) float g_poolpart[BDIM*NC*3*DMODEL];
__device__ __align__(256) float g_pooled[BDIM*3*DMODEL];
__device__ __align__(256) float g_coeffs[BDIM*3];

struct PtrTriple { const float* p[3]; };

// ---------------- shared epilogue ----------------
template<int MODE>
__device__ __forceinline__ void epi(int z, int row, int col, int N, float v,
    float* C, long cB, int ldc, int cColOff,
    const float* bias, long biasB,
    const PtrTriple& addTri, int ldadd, const float* coeffs)
{
    if (col >= N) return;
    if (MODE == 0) {
        (C + (long)z * cB)[(long)row * ldc + col] = v;
    } else if (MODE == 1) {
        float x = v + bias[z * biasB + col];
        (C + (long)z * cB)[(long)row * ldc + col] =
            fmaxf(x, 0.f) + log1pf(expf(-fabsf(x)));
    } else if (MODE == 2) {
        C[(long)row * ldc + col + z * cColOff] =
            v + addTri.p[z][(long)row * ldadd + col];
    } else { // MODE 3
        int bidx = row >> 11;   // row / SEQ
        float c0 = coeffs[bidx * 3 + 0];
        float c1 = coeffs[bidx * 3 + 1];
        float c2 = coeffs[bidx * 3 + 2];
        const float* mrow = addTri.p[0] + (long)row * ldadd;
        C[(long)row * ldc + col] = v + bias[col]
            + c0 * mrow[col] + c1 * mrow[col + 256] + c2 * mrow[col + 512];
    }
}

#if HAS_TC
// ---------------- tcgen05 helpers (sm_103a) ----------------
__device__ __forceinline__ uint32_t s2u(const void* p) {
    uint32_t a;
    asm("{ .reg .u64 t; cvta.to.shared.u64 t, %1; cvt.u32.u64 %0, t; }"
        : "=r"(a) : "l"(p));
    return a;
}
#define TC_ALLOC(sm, n) \
    asm volatile("tcgen05.alloc.cta_group::1.sync.aligned.shared::cta.b32 [%0], %1;" \
                 :: "r"(sm), "r"(n) : "memory")
#define TC_RELINQ() \
    asm volatile("tcgen05.relinquish_alloc_permit.cta_group::1.sync.aligned;")
#define TC_DEALLOC(t, n) \
    asm volatile("tcgen05.dealloc.cta_group::1.sync.aligned.b32 %0, %1;" :: "r"(t), "r"(n))
#define MBAR_INIT(a, c) \
    asm volatile("mbarrier.init.shared.b64 [%0], %1;" :: "r"(a), "r"(c) : "memory")
#define TC_COMMIT(a) \
    asm volatile("tcgen05.commit.cta_group::1.mbarrier::arrive::one.shared::cluster.b64 [%0];" \
                 :: "r"(a) : "memory")
#define TC_FENCE_AFTER()  asm volatile("tcgen05.fence::after_thread_sync;"  ::: "memory")
#define TC_FENCE_BEFORE() asm volatile("tcgen05.fence::before_thread_sync;" ::: "memory")
#define TC_WAIT_LD()      asm volatile("tcgen05.wait::ld.sync.aligned;"     ::: "memory")
#define FENCE_PROXY()     asm volatile("fence.proxy.async.shared::cta;"     ::: "memory")

#define MBAR_WAIT(mbar_smem_addr, phase_parity) do { \
    uint32_t _mbar = (uint32_t)(mbar_smem_addr); \
    uint32_t _parity = (uint32_t)(phase_parity); \
    uint32_t _done; \
    asm volatile( \
        "{\n\t" \
        ".reg .pred p;\n\t" \
        "mbarrier.try_wait.parity.acquire.cta.shared::cta.b64 p, [%1], %2;\n\t" \
        "selp.b32 %0, 1, 0, p;\n\t" \
        "}" \
        : "=r"(_done) : "r"(_mbar), "r"(_parity) : "memory"); \
    if (!_done) { \
        asm volatile( \
            "{\n\t" \
            ".reg .pred P1;\n\t" \
            "WAIT_LOOP_%=:\n\t" \
            "mbarrier.try_wait.parity.acquire.cta.shared::cta.b64 P1, [%0], %1, 0x989680;\n\t" \
            "@P1 bra.uni WAIT_DONE_%=;\n\t" \
            "bra.uni WAIT_LOOP_%=;\n\t" \
            "WAIT_DONE_%=:\n\t" \
            "}" \
            :: "r"(_mbar), "r"(_parity) : "memory"); \
    } \
} while(0)

#define LDTM32(r, tmem_addr) \
    asm volatile( \
        "tcgen05.ld.sync.aligned.32x32b.x32.b32 " \
        "{%0, %1, %2, %3, %4, %5, %6, %7, " \
        " %8, %9, %10, %11, %12, %13, %14, %15, " \
        " %16, %17, %18, %19, %20, %21, %22, %23, " \
        " %24, %25, %26, %27, %28, %29, %30, %31}, [%32];" \
        : "=r"((r)[0]),  "=r"((r)[1]),  "=r"((r)[2]),  "=r"((r)[3]), \
          "=r"((r)[4]),  "=r"((r)[5]),  "=r"((r)[6]),  "=r"((r)[7]), \
          "=r"((r)[8]),  "=r"((r)[9]),  "=r"((r)[10]), "=r"((r)[11]), \
          "=r"((r)[12]), "=r"((r)[13]), "=r"((r)[14]), "=r"((r)[15]), \
          "=r"((r)[16]), "=r"((r)[17]), "=r"((r)[18]), "=r"((r)[19]), \
          "=r"((r)[20]), "=r"((r)[21]), "=r"((r)[22]), "=r"((r)[23]), \
          "=r"((r)[24]), "=r"((r)[25]), "=r"((r)[26]), "=r"((r)[27]), \
          "=r"((r)[28]), "=r"((r)[29]), "=r"((r)[30]), "=r"((r)[31]) \
        : "r"(tmem_addr))

__device__ __forceinline__ void mma_tf32(uint32_t d, uint64_t ad, uint64_t bd,
                                         uint32_t idesc, bool acc) {
    uint32_t en = acc ? 1u : 0u, z = 0u;
    asm volatile(
        "{\n\t"
        ".reg .pred p;\n\t"
        "setp.ne.u32 p, %5, 0;\n\t"
        "tcgen05.mma.cta_group::1.kind::tf32 [%0], %1, %2, %3, {%4, %4, %4, %4}, p;\n\t"
        "}"
        :: "r"(d), "l"(ad), "l"(bd), "r"(idesc), "r"(z), "r"(en) : "memory");
}

__device__ __forceinline__ float tf32r(float x) {
    float y;
    asm("cvt.rna.tf32.f32 %0, %1;" : "=f"(y) : "f"(x));
    return y;
}

// SW128 descriptor base: layout=SW128(2), version=1(Blackwell), SBO=64, LBO=1
static __device__ __forceinline__ uint64_t desc_base(uint32_t addr) {
    const uint64_t B = (2ull << 61) | (1ull << 46) | (64ull << 32) | (1ull << 16);
    return B | ((uint64_t)(addr >> 4) & 0x3FFFull);
}
#endif // HAS_TC

// ---------------- GEMM: C = A(MxK) * B(NxK)^T, tile 128 x BN ---------------
// MODE 0: plain   MODE 1: softplus(acc + bias[z][col])
// MODE 2: acc + addTri.p[z][row*ldadd+col] -> C[row*ldc+col+z*cColOff]
// MODE 3: acc + bias[col] + sum_s coeffs[b][s]*addTri.p[0][row*ldadd+s*256+col]
template<int BN, int MODE, bool ZINIT>
__global__ void __launch_bounds__(256)
tgemm(const float* __restrict__ A, long aB, int lda,
      const float* __restrict__ B, long bB, int ldb,
      float* __restrict__ C, long cB, int ldc, int cColOff,
      int N, int K,
      const float* __restrict__ bias, long biasB,
      PtrTriple addTri, int ldadd,
      const float* __restrict__ coeffs)
{
    extern __shared__ __align__(1024) char smem[];
    int tid = threadIdx.x;
    int z = blockIdx.z;
    const float* Ab = A + (long)z * aB + (long)blockIdx.y * 128 * lda;
    const float* Bb = B + (long)z * bB + (long)blockIdx.x * BN * ldb;
    int bRow0 = blockIdx.x * BN;

#if HAS_TC
    // ================= tensor-core tf32 path =================
    constexpr int KC = 64;
    constexpr int A_BYTES = 128 * KC * 4;          // 32 KB
    constexpr int B_BYTES = BN * KC * 4;
    uint32_t sbase = s2u(smem);
    uint32_t sCtrl = sbase + A_BYTES + B_BYTES;    // [0]=tmem ptr, [8]=mbar
    int wid = tid >> 5, lane = tid & 31;

    if (wid == 0) { TC_ALLOC(sCtrl, BN); TC_RELINQ(); }
    if (tid == 0) MBAR_INIT(sCtrl + 8, 1);
    if (ZINIT) {
        uint4 zero = make_uint4(0u, 0u, 0u, 0u);
        for (int i = tid; i < (A_BYTES + B_BYTES) / 16; i += 256)
            ((uint4*)smem)[i] = zero;
    }
    __syncthreads();
    uint32_t tmem;
    asm volatile("ld.shared.b32 %0, [%1];" : "=r"(tmem) : "r"(sCtrl));

    uint64_t adesc0 = desc_base(sbase);
    uint64_t bdesc0 = desc_base(sbase + A_BYTES);
    const uint32_t idesc = 0x910u | ((uint32_t)(BN / 8) << 17) | (8u << 24);

    const int nch = (K + KC - 1) / KC;
    for (int c = 0; c < nch; c++) {
        int kc0 = c * KC;
        #pragma unroll 2
        for (int i = tid; i < 128 * 16; i += 256) {
            int row = i >> 4, e4 = i & 15;
            int ke = kc0 + e4 * 4;
            if (!ZINIT || ke < K) {
                float4 v = *(const float4*)(Ab + (long)row * lda + ke);
                v.x = tf32r(v.x); v.y = tf32r(v.y); v.z = tf32r(v.z); v.w = tf32r(v.w);
                uint32_t byt = (uint32_t)(((row >> 3) + (e4 >> 3) * 16) * 1024
                               + (row & 7) * 128 + (e4 & 7) * 16);
                byt ^= (byt >> 3) & 0x70;
                *(float4*)(smem + byt) = v;
            }
        }
        #pragma unroll 2
        for (int i = tid; i < BN * 16; i += 256) {
            int row = i >> 4, e4 = i & 15;
            int ke = kc0 + e4 * 4;
            if (!ZINIT || (bRow0 + row < N && ke < K)) {
                float4 v = *(const float4*)(Bb + (long)row * ldb + ke);
                v.x = tf32r(v.x); v.y = tf32r(v.y); v.z = tf32r(v.z); v.w = tf32r(v.w);
                uint32_t byt = (uint32_t)(((row >> 3) + (e4 >> 3) * (BN >> 3)) * 1024
                               + (row & 7) * 128 + (e4 & 7) * 16);
                byt ^= (byt >> 3) & 0x70;
                *(float4*)(smem + A_BYTES + byt) = v;
            }
        }
        FENCE_PROXY();
        __syncthreads();
        if (tid == 0) {
            int kleft = K - kc0; if (kleft > KC) kleft = KC;
            int ks = (kleft + 7) >> 3;
            for (int s = 0; s < ks; s++) {
                uint64_t ad = adesc0 + (uint64_t)((s >> 2) * 1024 + (s & 3) * 2);
                uint64_t bd = bdesc0 + (uint64_t)((s >> 2) * ((BN >> 3) * 64) + (s & 3) * 2);
                mma_tf32(tmem, ad, bd, idesc, (c > 0) || (s > 0));
            }
            TC_COMMIT(sCtrl + 8);
        }
        MBAR_WAIT(sCtrl + 8, c & 1);
        __syncthreads();
    }

    TC_FENCE_AFTER();
    if (wid < 4) {
        int row = blockIdx.y * 128 + wid * 32 + lane;
        #pragma unroll
        for (int cc = 0; cc < BN / 32; cc++) {
            uint32_t r[32];
            LDTM32(r, tmem + cc * 32);
            TC_WAIT_LD();
            int col0 = bRow0 + cc * 32;
            #pragma unroll
            for (int j = 0; j < 32; j++)
                epi<MODE>(z, row, col0 + j, N, __uint_as_float(r[j]),
                          C, cB, ldc, cColOff, bias, biasB, addTri, ldadd, coeffs);
        }
        TC_FENCE_BEFORE();
    }
    __syncthreads();
    if (wid == 0) TC_DEALLOC(tmem, BN);

#else
    // ================= SIMT fallback (round-2 tile) =================
    constexpr int BK = 8;
    constexpr int TM = 8;
    constexpr int TN = (BN == 128) ? 8 : 4;
    float (*As)[128 + 4] = (float(*)[128 + 4])smem;
    float (*Bs)[BN + 4]  = (float(*)[BN + 4])(smem + BK * (128 + 4) * 4);

    int tn = tid % (BN / TN);
    int tm = tid / (BN / TN);

    float acc[TM][TN];
    #pragma unroll
    for (int i = 0; i < TM; i++)
        #pragma unroll
        for (int j = 0; j < TN; j++) acc[i][j] = 0.f;

    float4 ra, rb;
    bool aAct = (tid * 4 < 128 * BK);
    bool bAct = (tid * 4 < BN * BK);
    int aR = (tid * 4) / BK, aC = (tid * 4) % BK;
    int bR = (tid * 4) / BK, bC = (tid * 4) % BK;

    if (aAct) ra = *(const float4*)(Ab + (long)aR * lda + aC);
    if (bAct) {
        if (bRow0 + bR < N) rb = *(const float4*)(Bb + (long)bR * ldb + bC);
        else rb = make_float4(0.f, 0.f, 0.f, 0.f);
    }

    for (int k0 = 0; k0 < K; k0 += BK) {
        if (aAct) {
            As[aC + 0][aR] = ra.x; As[aC + 1][aR] = ra.y;
            As[aC + 2][aR] = ra.z; As[aC + 3][aR] = ra.w;
        }
        if (bAct) {
            Bs[bC + 0][bR] = rb.x; Bs[bC + 1][bR] = rb.y;
            Bs[bC + 2][bR] = rb.z; Bs[bC + 3][bR] = rb.w;
        }
        __syncthreads();
        int kn = k0 + BK;
        if (kn < K) {
            if (aAct) ra = *(const float4*)(Ab + (long)aR * lda + kn + aC);
            if (bAct) {
                if (bRow0 + bR < N) rb = *(const float4*)(Bb + (long)bR * ldb + kn + bC);
                else rb = make_float4(0.f, 0.f, 0.f, 0.f);
            }
        }
        #pragma unroll
        for (int k = 0; k < BK; k++) {
            float am[TM], bn[TN];
            #pragma unroll
            for (int i = 0; i < TM; i += 4)
                *(float4*)&am[i] = *(const float4*)&As[k][tm * TM + i];
            #pragma unroll
            for (int j = 0; j < TN; j += 4)
                *(float4*)&bn[j] = *(const float4*)&Bs[k][tn * TN + j];
            #pragma unroll
            for (int i = 0; i < TM; i++)
                #pragma unroll
                for (int j = 0; j < TN; j++)
                    acc[i][j] = fmaf(am[i], bn[j], acc[i][j]);
        }
        __syncthreads();
    }

    int row0 = blockIdx.y * 128 + tm * TM;
    int col0 = blockIdx.x * BN + tn * TN;
    #pragma unroll
    for (int i = 0; i < TM; i++)
        #pragma unroll
        for (int j = 0; j < TN; j++)
            epi<MODE>(z, row0 + i, col0 + j, N, acc[i][j],
                      C, cB, ldc, cColOff, bias, biasB, addTri, ldadd, coeffs);
#endif
}

// ---------------- layernorm ----------------
__global__ void layernorm_kernel(PtrTriple xs, const float* __restrict__ w,
                                 const float* __restrict__ bb) {
    int row = blockIdx.x;
    int s = row / NROWS;
    int r = row - s * NROWS;
    const float* x = xs.p[s] + (long)r * DMODEL;
    int t = threadIdx.x;
    float v = x[t];
    float s1 = v, s2 = v * v;
    #pragma unroll
    for (int o = 16; o; o >>= 1) {
        s1 += __shfl_xor_sync(0xffffffffu, s1, o);
        s2 += __shfl_xor_sync(0xffffffffu, s2, o);
    }
    __shared__ float smA[8], smB[8];
    if ((t & 31) == 0) { smA[t >> 5] = s1; smB[t >> 5] = s2; }
    __syncthreads();
    if (t < 8) {
        float a = smA[t], b = smB[t];
        #pragma unroll
        for (int o = 4; o; o >>= 1) {
            a += __shfl_xor_sync(0xffu, a, o);
            b += __shfl_xor_sync(0xffu, b, o);
        }
        if (t == 0) { smA[0] = a; smB[0] = b; }
    }
    __syncthreads();
    float mean = smA[0] * (1.0f / DMODEL);
    float var  = smB[0] * (1.0f / DMODEL) - mean * mean;
    float inv  = rsqrtf(var + 1e-5f);
    g_xn[(long)row * DMODEL + t] = (v - mean) * inv * w[s * DMODEL + t] + bb[s * DMODEL + t];
}

// ---------------- causal depthwise conv (DC=4) + SiLU ----------------
__global__ void conv_silu_kernel(const float* __restrict__ conv_w,
                                 const float* __restrict__ conv_b) {
    int idx = blockIdx.x * blockDim.x + threadIdx.x;
    if (idx >= NSTREAM * NROWS * DINNER) return;
    int d    = idx % DINNER;
    int rest = idx / DINNER;
    int n    = rest % SEQ;
    int sb   = rest / SEQ;
    int si   = sb / BDIM;
    const float* base = g_xz + (long)sb * SEQ * (2 * DINNER) + d;
    const float* cw   = conv_w + (si * DINNER + d) * DCONV;
    float acc = conv_b[si * DINNER + d];
    #pragma unroll
    for (int k = 0; k < DCONV; k++) {
        int m = n + k - (DCONV - 1);
        if (m >= 0) acc = fmaf(base[(long)m * (2 * DINNER)], cw[k], acc);
    }
    g_xa[idx] = acc / (1.f + __expf(-acc));
}

// ------- chunked selective scan: block = 1 channel, 16 chunks x 16 states ---
__global__ void __launch_bounds__(NC*SSTATE)
scan_kernel(const float* __restrict__ A_log, const float* __restrict__ Dp) {
    int ch = blockIdx.x;
    int si = ch / (BDIM * DINNER);
    int rem = ch - si * (BDIM * DINNER);
    int b = rem / DINNER;
    int d = rem - b * DINNER;
    int t = threadIdx.x;
    int chunk = t >> 4;
    int sl = t & 15;
    long sb = (long)si * BDIM + b;

    const float* dt = g_dt + sb * SEQ * DINNER + d;
    const float* xa = g_xa + sb * SEQ * DINNER + d;
    const float* xd = g_xdbl + sb * SEQ * XDBL;
    float a = -__expf(A_log[(si * DINNER + d) * SSTATE + sl]);

    int n0 = chunk * TCH;

    float h = 0.f, sdt = 0.f;
    #pragma unroll 2
    for (int n = n0; n < n0 + TCH; n++) {
        float dtv = dt[(long)n * DINNER];
        float xav = xa[(long)n * DINNER];
        float Bv  = xd[n * XDBL + 16 + sl];
        float e = __expf(dtv * a);
        h = fmaf(e, h, (dtv * Bv) * xav);
        sdt += dtv;
    }

    __shared__ float sP[NC][SSTATE], sL[NC][SSTATE], sH[NC][SSTATE];
    sP[chunk][sl] = __expf(a * sdt);
    sL[chunk][sl] = h;
    __syncthreads();

    if (t < SSTATE) {
        float H = 0.f;
        #pragma unroll
        for (int c = 0; c < NC; c++) {
            sH[c][t] = H;
            H = fmaf(sP[c][t], H, sL[c][t]);
        }
    }
    __syncthreads();

    float hh = sH[chunk][sl];
    float Dpd = Dp[si * DINNER + d];
    const float* zz = g_xz + sb * SEQ * (2 * DINNER) + DINNER + d;
    float* yo = g_y + sb * SEQ * DINNER + d;
    #pragma unroll 2
    for (int n = n0; n < n0 + TCH; n++) {
        float dtv = dt[(long)n * DINNER];
        float xav = xa[(long)n * DINNER];
        float Bv  = xd[n * XDBL + 16 + sl];
        float Cv  = xd[n * XDBL + 32 + sl];
        float e = __expf(dtv * a);
        hh = fmaf(e, hh, (dtv * Bv) * xav);
        float p = hh * Cv;
        p += __shfl_xor_sync(0xffffffffu, p, 8);
        p += __shfl_xor_sync(0xffffffffu, p, 4);
        p += __shfl_xor_sync(0xffffffffu, p, 2);
        p += __shfl_xor_sync(0xffffffffu, p, 1);
        if (sl == 0) {
            float zv = zz[(long)n * (2 * DINNER)];
            float sz = zv / (1.f + __expf(-zv));
            yo[(long)n * DINNER] = (p + xav * Dpd) * sz;
        }
    }
}

// ---------------- mean pool over sequence (two stages) ----------------
__global__ void pool1_kernel() {
    int c = blockIdx.x;
    int b = blockIdx.y;
    int j = threadIdx.x;
    const float* base = g_multi + ((long)b * SEQ + c * (SEQ / NC)) * 768 + j;
    float s = 0.f;
    #pragma unroll 4
    for (int n = 0; n < SEQ / NC; n++) s += base[(long)n * 768];
    g_poolpart[((long)b * NC + c) * 768 + j] = s;
}
__global__ void pool2_kernel() {
    int b = blockIdx.x;
    int j = threadIdx.x;
    float s = 0.f;
    #pragma unroll
    for (int c = 0; c < NC; c++) s += g_poolpart[((long)b * NC + c) * 768 + j];
    g_pooled[b * 768 + j] = s * (1.f / SEQ);
}

// ---------------- aggregation coefficients ----------------
__global__ void coeffs_kernel(const float* __restrict__ w1, const float* __restrict__ b1,
                              const float* __restrict__ w2, const float* __restrict__ b2,
                              const float* __restrict__ temp) {
    int b = blockIdx.x;
    int d = threadIdx.x;
    const float* p = g_pooled + b * 768;
    const float* wr = w1 + (long)d * 768;
    float acc = b1[d];
    for (int e = 0; e < 768; e++) acc = fmaf(p[e], wr[e], acc);
    float x = acc;
    float cc = 0.7978845608028654f * (x + 0.044715f * x * x * x);
    float hg = 0.5f * x * (1.f + tanhf(cc));

    __shared__ float red[256];
    float logits[3];
    for (int k = 0; k < 3; k++) {
        red[d] = hg * w2[k * 256 + d];
        __syncthreads();
        for (int o = 128; o; o >>= 1) {
            if (d < o) red[d] += red[d + o];
            __syncthreads();
        }
        logits[k] = red[0] + b2[k];
        __syncthreads();
    }
    if (d == 0) {
        float m = fmaxf(logits[0], fmaxf(logits[1], logits[2]));
        float e0 = expf(logits[0] - m), e1 = expf(logits[1] - m), e2 = expf(logits[2] - m);
        float s = e0 + e1 + e2; e0 /= s; e1 /= s; e2 /= s;
        float invt = 1.f / (temp[0] + 1e-6f);
        float mm = fmaxf(e0, fmaxf(e1, e2)) * invt;
        float f0 = expf(e0 * invt - mm), f1 = expf(e1 * invt - mm), f2 = expf(e2 * invt - mm);
        float ss = f0 + f1 + f2;
        g_coeffs[b * 3 + 0] = f0 / ss;
        g_coeffs[b * 3 + 1] = f1 / ss;
        g_coeffs[b * 3 + 2] = f2 / ss;
    }
}

// ---------------- launch ----------------
extern "C" void kernel_launch(void* const* d_in, const int* in_sizes, int n_in,
                              void* d_out, int out_size) {
    const float* edge    = (const float*)d_in[0];
    const float* blob    = (const float*)d_in[1];
    const float* spec    = (const float*)d_in[2];
    const float* norm_w  = (const float*)d_in[3];
    const float* norm_b  = (const float*)d_in[4];
    const float* in_w    = (const float*)d_in[5];
    const float* conv_w  = (const float*)d_in[6];
    const float* conv_b  = (const float*)d_in[7];
    const float* xproj_w = (const float*)d_in[8];
    const float* dt_w    = (const float*)d_in[9];
    const float* dt_b    = (const float*)d_in[10];
    const float* A_log   = (const float*)d_in[11];
    const float* Dp      = (const float*)d_in[12];
    const float* out_w   = (const float*)d_in[13];
    const float* temp    = (const float*)d_in[14];
    const float* agg_w1  = (const float*)d_in[15];
    const float* agg_b1  = (const float*)d_in[16];
    const float* agg_w2  = (const float*)d_in[17];
    const float* agg_b2  = (const float*)d_in[18];
    const float* proj_w  = (const float*)d_in[19];
    const float* proj_b  = (const float*)d_in[20];
    float* out = (float*)d_out;

    float *xn, *xz, *xa, *xdbl, *dtb, *yb, *multi, *coef;
    cudaGetSymbolAddress((void**)&xn,    g_xn);
    cudaGetSymbolAddress((void**)&xz,    g_xz);
    cudaGetSymbolAddress((void**)&xa,    g_xa);
    cudaGetSymbolAddress((void**)&xdbl,  g_xdbl);
    cudaGetSymbolAddress((void**)&dtb,   g_dt);
    cudaGetSymbolAddress((void**)&yb,    g_y);
    cudaGetSymbolAddress((void**)&multi, g_multi);
    cudaGetSymbolAddress((void**)&coef,  g_coeffs);

    PtrTriple tri;  tri.p[0] = edge; tri.p[1] = blob; tri.p[2] = spec;
    PtrTriple tri0; tri0.p[0] = nullptr; tri0.p[1] = nullptr; tri0.p[2] = nullptr;
    PtrTriple triM; triM.p[0] = multi; triM.p[1] = nullptr; triM.p[2] = nullptr;

    const int SM128 = 128*64*4 + 128*64*4 + 64;   // 65600
    const int SM64  = 128*64*4 +  64*64*4 + 64;   // 49216
    cudaFuncSetAttribute(tgemm<128,0,false>, cudaFuncAttributeMaxDynamicSharedMemorySize, SM128);
    cudaFuncSetAttribute(tgemm<64, 0,true >, cudaFuncAttributeMaxDynamicSharedMemorySize, SM64);
    cudaFuncSetAttribute(tgemm<128,1,true >, cudaFuncAttributeMaxDynamicSharedMemorySize, SM128);
    cudaFuncSetAttribute(tgemm<128,2,false>, cudaFuncAttributeMaxDynamicSharedMemorySize, SM128);
    cudaFuncSetAttribute(tgemm<128,3,false>, cudaFuncAttributeMaxDynamicSharedMemorySize, SM128);

    // 1) layernorm
    layernorm_kernel<<<NSTREAM * NROWS, 256>>>(tri, norm_w, norm_b);

    // 2) in_proj: xz = xn @ in_w^T  (M=4096, N=1024, K=256 per stream)
    tgemm<128,0,false><<<dim3(8, 32, 3), 256, SM128>>>(
        xn, (long)NROWS*DMODEL, DMODEL,
        in_w, (long)1024*DMODEL, DMODEL,
        xz, (long)NROWS*1024, 1024, 0,
        1024, DMODEL, nullptr, 0, tri0, 0, nullptr);

    // 3) conv + silu
    conv_silu_kernel<<<(NSTREAM*NROWS*DINNER)/256, 256>>>(conv_w, conv_b);

    // 4) xproj: x_dbl = xa @ xproj_w^T (M=4096, N=48, K=512)
    tgemm<64,0,true><<<dim3(1, 32, 3), 256, SM64>>>(
        xa, (long)NROWS*DINNER, DINNER,
        xproj_w, (long)XDBL*DINNER, DINNER,
        xdbl, (long)NROWS*XDBL, XDBL, 0,
        XDBL, DINNER, nullptr, 0, tri0, 0, nullptr);

    // 5) dt = softplus(x_dbl[:, :16] @ dt_w^T + dt_b) (M=4096, N=512, K=16)
    tgemm<128,1,true><<<dim3(4, 32, 3), 256, SM128>>>(
        xdbl, (long)NROWS*XDBL, XDBL,
        dt_w, (long)DINNER*16, 16,
        dtb, (long)NROWS*DINNER, DINNER, 0,
        DINNER, 16, dt_b, DINNER, tri0, 0, nullptr);

    // 6) chunked selective scan (+ D skip + silu(z) gate)
    scan_kernel<<<NSTREAM*BDIM*DINNER, NC*SSTATE>>>(A_log, Dp);

    // 7) out_proj + residual into concat layout multi (B,N,3*256)
    tgemm<128,2,false><<<dim3(2, 32, 3), 256, SM128>>>(
        yb, (long)NROWS*DINNER, DINNER,
        out_w, (long)DMODEL*DINNER, DINNER,
        multi, 0, 3*DMODEL, DMODEL,
        DMODEL, DINNER, nullptr, 0, tri, DMODEL, nullptr);

    // 8) mean pool over N (two stage)
    pool1_kernel<<<dim3(NC, BDIM), 768>>>();
    pool2_kernel<<<BDIM, 768>>>();

    // 9) aggregation coefficients (gelu -> double softmax)
    coeffs_kernel<<<BDIM, 256>>>(agg_w1, agg_b1, agg_w2, agg_b2, temp);

    // 10) final: out = multi @ proj_w^T + proj_b + coeff-weighted streams
    tgemm<128,3,false><<<dim3(2, 32, 1), 256, SM128>>>(
        multi, 0, 3*DMODEL,
        proj_w, 0, 3*DMODEL,
        out, 0, DMODEL, 0,
        DMODEL, 3*DMODEL, proj_b, 0, triM, 3*DMODEL, coef);
}

// round 5
// speedup vs baseline: 3.4353x; 1.3366x over previous
#include <cuda_runtime.h>
#include <cstdint>
#include <math.h>

#define BDIM 2
#define SEQ 2048
#define DMODEL 256
#define SSTATE 16
#define DCONV 4
#define DINNER 512
#define NROWS (BDIM*SEQ)   /* 4096 rows per stream */
#define NSTREAM 3
#define XDBL 48            /* dt(16) + B(16) + C(16) */
#define NC 16              /* scan chunks */
#define TCH (SEQ/NC)       /* 128 steps per chunk */
#define NSB (NSTREAM*BDIM) /* 6 */
#define CHG 128            /* channels per scan block */

#if defined(__CUDA_ARCH_FEAT_SM103_ALL) \
 || (defined(__CUDA_ARCH_SPECIFIC__) && (__CUDA_ARCH_SPECIFIC__ == 1030)) \
 || (defined(__CUDA_ARCH_FAMILY_SPECIFIC__) && (__CUDA_ARCH_FAMILY_SPECIFIC__ == 1030))
#define HAS_TC 1
#else
#define HAS_TC 0
#endif

// ---------------- scratch ----------------
__device__ __align__(256) float g_xn   [NSTREAM*NROWS*DMODEL];
__device__ __align__(256) float g_xz   [NSTREAM*NROWS*2*DINNER];
__device__ __align__(256) float g_xa   [NSTREAM*NROWS*DINNER];
__device__ __align__(256) float g_xdbl [NSTREAM*NROWS*XDBL];
__device__ __align__(256) float g_dt   [NSTREAM*NROWS*DINNER];
__device__ __align__(256) float g_y    [NSTREAM*NROWS*DINNER];
__device__ __align__(256) float g_multi[NROWS*3*DMODEL];
__device__ __align__(256) float g_P    [NC*NSB*DINNER*SSTATE];
__device__ __align__(256) float g_L    [NC*NSB*DINNER*SSTATE];
__device__ __align__(256) float g_H    [NC*NSB*DINNER*SSTATE];
__device__ __align__(256) float g_poolpart[BDIM*NC*3*DMODEL];
__device__ __align__(256) float g_pooled[BDIM*3*DMODEL];
__device__ __align__(256) float g_coeffs[BDIM*3];

struct PtrTriple { const float* p[3]; };

// ---------------- shared epilogue ----------------
template<int MODE>
__device__ __forceinline__ void epi(int z, int row, int col, int N, float v,
    float* C, long cB, int ldc, int cColOff,
    const float* bias, long biasB,
    const PtrTriple& addTri, int ldadd, const float* coeffs)
{
    if (col >= N) return;
    if (MODE == 0) {
        (C + (long)z * cB)[(long)row * ldc + col] = v;
    } else if (MODE == 1) {
        float x = v + bias[z * biasB + col];
        (C + (long)z * cB)[(long)row * ldc + col] =
            fmaxf(x, 0.f) + log1pf(expf(-fabsf(x)));
    } else if (MODE == 2) {
        C[(long)row * ldc + col + z * cColOff] =
            v + addTri.p[z][(long)row * ldadd + col];
    } else { // MODE 3
        int bidx = row >> 11;
        float c0 = coeffs[bidx * 3 + 0];
        float c1 = coeffs[bidx * 3 + 1];
        float c2 = coeffs[bidx * 3 + 2];
        const float* mrow = addTri.p[0] + (long)row * ldadd;
        C[(long)row * ldc + col] = v + bias[col]
            + c0 * mrow[col] + c1 * mrow[col + 256] + c2 * mrow[col + 512];
    }
}

#if HAS_TC
// ---------------- tcgen05 helpers ----------------
__device__ __forceinline__ uint32_t s2u(const void* p) {
    uint32_t a;
    asm("{ .reg .u64 t; cvta.to.shared.u64 t, %1; cvt.u32.u64 %0, t; }"
        : "=r"(a) : "l"(p));
    return a;
}
#define TC_ALLOC(sm, n) \
    asm volatile("tcgen05.alloc.cta_group::1.sync.aligned.shared::cta.b32 [%0], %1;" \
                 :: "r"(sm), "r"(n) : "memory")
#define TC_RELINQ() \
    asm volatile("tcgen05.relinquish_alloc_permit.cta_group::1.sync.aligned;")
#define TC_DEALLOC(t, n) \
    asm volatile("tcgen05.dealloc.cta_group::1.sync.aligned.b32 %0, %1;" :: "r"(t), "r"(n))
#define MBAR_INIT(a, c) \
    asm volatile("mbarrier.init.shared.b64 [%0], %1;" :: "r"(a), "r"(c) : "memory")
#define TC_COMMIT(a) \
    asm volatile("tcgen05.commit.cta_group::1.mbarrier::arrive::one.shared::cluster.b64 [%0];" \
                 :: "r"(a) : "memory")
#define TC_FENCE_AFTER()  asm volatile("tcgen05.fence::after_thread_sync;"  ::: "memory")
#define TC_FENCE_BEFORE() asm volatile("tcgen05.fence::before_thread_sync;" ::: "memory")
#define TC_WAIT_LD()      asm volatile("tcgen05.wait::ld.sync.aligned;"     ::: "memory")
#define FENCE_PROXY()     asm volatile("fence.proxy.async.shared::cta;"     ::: "memory")

#define MBAR_WAIT(mbar_smem_addr, phase_parity) do { \
    uint32_t _mbar = (uint32_t)(mbar_smem_addr); \
    uint32_t _parity = (uint32_t)(phase_parity); \
    uint32_t _done; \
    asm volatile( \
        "{\n\t" \
        ".reg .pred p;\n\t" \
        "mbarrier.try_wait.parity.acquire.cta.shared::cta.b64 p, [%1], %2;\n\t" \
        "selp.b32 %0, 1, 0, p;\n\t" \
        "}" \
        : "=r"(_done) : "r"(_mbar), "r"(_parity) : "memory"); \
    if (!_done) { \
        asm volatile( \
            "{\n\t" \
            ".reg .pred P1;\n\t" \
            "WAIT_LOOP_%=:\n\t" \
            "mbarrier.try_wait.parity.acquire.cta.shared::cta.b64 P1, [%0], %1, 0x989680;\n\t" \
            "@P1 bra.uni WAIT_DONE_%=;\n\t" \
            "bra.uni WAIT_LOOP_%=;\n\t" \
            "WAIT_DONE_%=:\n\t" \
            "}" \
            :: "r"(_mbar), "r"(_parity) : "memory"); \
    } \
} while(0)

#define LDTM32(r, tmem_addr) \
    asm volatile( \
        "tcgen05.ld.sync.aligned.32x32b.x32.b32 " \
        "{%0, %1, %2, %3, %4, %5, %6, %7, " \
        " %8, %9, %10, %11, %12, %13, %14, %15, " \
        " %16, %17, %18, %19, %20, %21, %22, %23, " \
        " %24, %25, %26, %27, %28, %29, %30, %31}, [%32];" \
        : "=r"((r)[0]),  "=r"((r)[1]),  "=r"((r)[2]),  "=r"((r)[3]), \
          "=r"((r)[4]),  "=r"((r)[5]),  "=r"((r)[6]),  "=r"((r)[7]), \
          "=r"((r)[8]),  "=r"((r)[9]),  "=r"((r)[10]), "=r"((r)[11]), \
          "=r"((r)[12]), "=r"((r)[13]), "=r"((r)[14]), "=r"((r)[15]), \
          "=r"((r)[16]), "=r"((r)[17]), "=r"((r)[18]), "=r"((r)[19]), \
          "=r"((r)[20]), "=r"((r)[21]), "=r"((r)[22]), "=r"((r)[23]), \
          "=r"((r)[24]), "=r"((r)[25]), "=r"((r)[26]), "=r"((r)[27]), \
          "=r"((r)[28]), "=r"((r)[29]), "=r"((r)[30]), "=r"((r)[31]) \
        : "r"(tmem_addr))

__device__ __forceinline__ void mma_tf32(uint32_t d, uint64_t ad, uint64_t bd,
                                         uint32_t idesc, bool acc) {
    uint32_t en = acc ? 1u : 0u, z = 0u;
    asm volatile(
        "{\n\t"
        ".reg .pred p;\n\t"
        "setp.ne.u32 p, %5, 0;\n\t"
        "tcgen05.mma.cta_group::1.kind::tf32 [%0], %1, %2, %3, {%4, %4, %4, %4}, p;\n\t"
        "}"
        :: "r"(d), "l"(ad), "l"(bd), "r"(idesc), "r"(z), "r"(en) : "memory");
}

__device__ __forceinline__ float tf32r(float x) {
    float y;
    asm("cvt.rna.tf32.f32 %0, %1;" : "=f"(y) : "f"(x));
    return y;
}

static __device__ __forceinline__ uint64_t desc_base(uint32_t addr) {
    const uint64_t B = (2ull << 61) | (1ull << 46) | (64ull << 32) | (1ull << 16);
    return B | ((uint64_t)(addr >> 4) & 0x3FFFull);
}
#endif // HAS_TC

// -------- GEMM: C = A(MxK) * B(NxK)^T, 128 x BN tile, 2-stage pipeline -----
template<int BN, int MODE, bool ZINIT>
__global__ void __launch_bounds__(256)
tgemm(const float* __restrict__ A, long aB, int lda,
      const float* __restrict__ B, long bB, int ldb,
      float* __restrict__ C, long cB, int ldc, int cColOff,
      int N, int K,
      const float* __restrict__ bias, long biasB,
      PtrTriple addTri, int ldadd,
      const float* __restrict__ coeffs)
{
    extern __shared__ __align__(1024) char smem[];
    int tid = threadIdx.x;
    int z = blockIdx.z;
    const float* Ab = A + (long)z * aB + (long)blockIdx.y * 128 * lda;
    const float* Bb = B + (long)z * bB + (long)blockIdx.x * BN * ldb;
    int bRow0 = blockIdx.x * BN;

#if HAS_TC
    constexpr int KC = 32;                 // rows are exactly 128B: canonical SW128
    constexpr int A_ST = 128 * KC * 4;     // 16 KB
    constexpr int B_ST = BN * KC * 4;
    constexpr int STAGE = A_ST + B_ST;
    uint32_t sbase = s2u(smem);
    uint32_t sCtrl = sbase + 2 * STAGE;    // [0]=tmem [8]=mbar0 [16]=mbar1
    int wid = tid >> 5, lane = tid & 31;

    if (wid == 0) { TC_ALLOC(sCtrl, BN); TC_RELINQ(); }
    if (tid == 0) { MBAR_INIT(sCtrl + 8, 1); MBAR_INIT(sCtrl + 16, 1); }
    if (ZINIT) {
        uint4 zero = make_uint4(0u, 0u, 0u, 0u);
        for (int i = tid; i < 2 * STAGE / 16; i += 256)
            ((uint4*)smem)[i] = zero;
    }
    __syncthreads();
    uint32_t tmem;
    asm volatile("ld.shared.b32 %0, [%1];" : "=r"(tmem) : "r"(sCtrl));

    const uint32_t idesc = 0x910u | ((uint32_t)(BN / 8) << 17) | (8u << 24);
    const int nch = (K + KC - 1) / KC;
    int ph[2] = {0, 0};

    for (int c = 0; c < nch; c++) {
        int s = c & 1;
        uint32_t stA = sbase + s * STAGE;
        uint32_t stB = stA + A_ST;
        if (c >= 2) { MBAR_WAIT(sCtrl + 8 + s * 8, ph[s]); ph[s] ^= 1; }
        int kc0 = c * KC;
        // A chunk: 128 rows x 32 floats (8 float4/row)
        #pragma unroll 2
        for (int i = tid; i < 128 * 8; i += 256) {
            int row = i >> 3, e4 = i & 7;
            int ke = kc0 + e4 * 4;
            if (!ZINIT || ke < K) {
                float4 v = *(const float4*)(Ab + (long)row * lda + ke);
                v.x = tf32r(v.x); v.y = tf32r(v.y); v.z = tf32r(v.z); v.w = tf32r(v.w);
                uint32_t byt = (uint32_t)(row * 128 + e4 * 16);
                byt ^= (byt >> 3) & 0x70;
                *(float4*)(smem + (stA - sbase) + byt) = v;
            }
        }
        // B chunk: BN rows x 32 floats
        #pragma unroll 2
        for (int i = tid; i < BN * 8; i += 256) {
            int row = i >> 3, e4 = i & 7;
            int ke = kc0 + e4 * 4;
            if (!ZINIT || (bRow0 + row < N && ke < K)) {
                float4 v = *(const float4*)(Bb + (long)row * ldb + ke);
                v.x = tf32r(v.x); v.y = tf32r(v.y); v.z = tf32r(v.z); v.w = tf32r(v.w);
                uint32_t byt = (uint32_t)(row * 128 + e4 * 16);
                byt ^= (byt >> 3) & 0x70;
                *(float4*)(smem + (stB - sbase) + byt) = v;
            }
        }
        FENCE_PROXY();
        __syncthreads();
        if (tid == 0) {
            uint64_t ad0 = desc_base(stA), bd0 = desc_base(stB);
            int kleft = K - kc0; if (kleft > KC) kleft = KC;
            int ks = (kleft + 7) >> 3;
            for (int st = 0; st < ks; st++)
                mma_tf32(tmem, ad0 + st * 2, bd0 + st * 2, idesc, (c > 0) || (st > 0));
            TC_COMMIT(sCtrl + 8 + s * 8);
        }
    }
    {
        int sl = (nch - 1) & 1;
        MBAR_WAIT(sCtrl + 8 + sl * 8, ph[sl]);
    }
    __syncthreads();

    TC_FENCE_AFTER();
    if (wid < 4) {
        int row = blockIdx.y * 128 + wid * 32 + lane;
        #pragma unroll
        for (int cc = 0; cc < BN / 32; cc++) {
            uint32_t r[32];
            LDTM32(r, tmem + cc * 32);
            TC_WAIT_LD();
            int col0 = bRow0 + cc * 32;
            #pragma unroll
            for (int j = 0; j < 32; j++)
                epi<MODE>(z, row, col0 + j, N, __uint_as_float(r[j]),
                          C, cB, ldc, cColOff, bias, biasB, addTri, ldadd, coeffs);
        }
        TC_FENCE_BEFORE();
    }
    __syncthreads();
    if (wid == 0) TC_DEALLOC(tmem, BN);

#else
    // ---------- SIMT fallback ----------
    constexpr int BK = 8;
    constexpr int TM = 8;
    constexpr int TN = (BN == 128) ? 8 : 4;
    float (*As)[128 + 4] = (float(*)[128 + 4])smem;
    float (*Bs)[BN + 4]  = (float(*)[BN + 4])(smem + BK * (128 + 4) * 4);

    int tn = tid % (BN / TN);
    int tm = tid / (BN / TN);

    float acc[TM][TN];
    #pragma unroll
    for (int i = 0; i < TM; i++)
        #pragma unroll
        for (int j = 0; j < TN; j++) acc[i][j] = 0.f;

    float4 ra, rb;
    bool aAct = (tid * 4 < 128 * BK);
    bool bAct = (tid * 4 < BN * BK);
    int aR = (tid * 4) / BK, aC = (tid * 4) % BK;
    int bR = (tid * 4) / BK, bC = (tid * 4) % BK;

    if (aAct) ra = *(const float4*)(Ab + (long)aR * lda + aC);
    if (bAct) {
        if (bRow0 + bR < N) rb = *(const float4*)(Bb + (long)bR * ldb + bC);
        else rb = make_float4(0.f, 0.f, 0.f, 0.f);
    }

    for (int k0 = 0; k0 < K; k0 += BK) {
        if (aAct) {
            As[aC + 0][aR] = ra.x; As[aC + 1][aR] = ra.y;
            As[aC + 2][aR] = ra.z; As[aC + 3][aR] = ra.w;
        }
        if (bAct) {
            Bs[bC + 0][bR] = rb.x; Bs[bC + 1][bR] = rb.y;
            Bs[bC + 2][bR] = rb.z; Bs[bC + 3][bR] = rb.w;
        }
        __syncthreads();
        int kn = k0 + BK;
        if (kn < K) {
            if (aAct) ra = *(const float4*)(Ab + (long)aR * lda + kn + aC);
            if (bAct) {
                if (bRow0 + bR < N) rb = *(const float4*)(Bb + (long)bR * ldb + kn + bC);
                else rb = make_float4(0.f, 0.f, 0.f, 0.f);
            }
        }
        #pragma unroll
        for (int k = 0; k < BK; k++) {
            float am[TM], bn[TN];
            #pragma unroll
            for (int i = 0; i < TM; i += 4)
                *(float4*)&am[i] = *(const float4*)&As[k][tm * TM + i];
            #pragma unroll
            for (int j = 0; j < TN; j += 4)
                *(float4*)&bn[j] = *(const float4*)&Bs[k][tn * TN + j];
            #pragma unroll
            for (int i = 0; i < TM; i++)
                #pragma unroll
                for (int j = 0; j < TN; j++)
                    acc[i][j] = fmaf(am[i], bn[j], acc[i][j]);
        }
        __syncthreads();
    }

    int row0 = blockIdx.y * 128 + tm * TM;
    int col0 = blockIdx.x * BN + tn * TN;
    #pragma unroll
    for (int i = 0; i < TM; i++)
        #pragma unroll
        for (int j = 0; j < TN; j++)
            epi<MODE>(z, row0 + i, col0 + j, N, acc[i][j],
                      C, cB, ldc, cColOff, bias, biasB, addTri, ldadd, coeffs);
#endif
}

// ---------------- layernorm ----------------
__global__ void layernorm_kernel(PtrTriple xs, const float* __restrict__ w,
                                 const float* __restrict__ bb) {
    int row = blockIdx.x;
    int s = row / NROWS;
    int r = row - s * NROWS;
    const float* x = xs.p[s] + (long)r * DMODEL;
    int t = threadIdx.x;
    float v = x[t];
    float s1 = v, s2 = v * v;
    #pragma unroll
    for (int o = 16; o; o >>= 1) {
        s1 += __shfl_xor_sync(0xffffffffu, s1, o);
        s2 += __shfl_xor_sync(0xffffffffu, s2, o);
    }
    __shared__ float smA[8], smB[8];
    if ((t & 31) == 0) { smA[t >> 5] = s1; smB[t >> 5] = s2; }
    __syncthreads();
    if (t < 8) {
        float a = smA[t], b = smB[t];
        #pragma unroll
        for (int o = 4; o; o >>= 1) {
            a += __shfl_xor_sync(0xffu, a, o);
            b += __shfl_xor_sync(0xffu, b, o);
        }
        if (t == 0) { smA[0] = a; smB[0] = b; }
    }
    __syncthreads();
    float mean = smA[0] * (1.0f / DMODEL);
    float var  = smB[0] * (1.0f / DMODEL) - mean * mean;
    float inv  = rsqrtf(var + 1e-5f);
    g_xn[(long)row * DMODEL + t] = (v - mean) * inv * w[s * DMODEL + t] + bb[s * DMODEL + t];
}

// ---------------- causal depthwise conv + SiLU ----------------
__global__ void conv_silu_kernel(const float* __restrict__ conv_w,
                                 const float* __restrict__ conv_b) {
    int idx = blockIdx.x * blockDim.x + threadIdx.x;
    if (idx >= NSTREAM * NROWS * DINNER) return;
    int d    = idx % DINNER;
    int rest = idx / DINNER;
    int n    = rest % SEQ;
    int sb   = rest / SEQ;
    int si   = sb / BDIM;
    const float* base = g_xz + (long)sb * SEQ * (2 * DINNER) + d;
    const float* cw   = conv_w + (si * DINNER + d) * DCONV;
    float acc = conv_b[si * DINNER + d];
    #pragma unroll
    for (int k = 0; k < DCONV; k++) {
        int m = n + k - (DCONV - 1);
        if (m >= 0) acc = fmaf(base[(long)m * (2 * DINNER)], cw[k], acc);
    }
    g_xa[idx] = acc / (1.f + __expf(-acc));
}

// ---------------- scan phase 1: per-chunk local scan ----------------
// block = (chunk, group, sb); thread = one channel; 16 states in registers.
__global__ void __launch_bounds__(CHG)
scan1_kernel(const float* __restrict__ A_log) {
    int chunk = blockIdx.x;
    int d = blockIdx.y * CHG + threadIdx.x;
    int sb = blockIdx.z;
    int si = sb / BDIM;
    int tid = threadIdx.x;
    int n0 = chunk * TCH;

    __shared__ float sB[TCH][16];
    {
        const float* xr = g_xdbl + ((long)sb * SEQ + n0) * XDBL;
        for (int i = tid; i < TCH * 16; i += CHG) {
            int r = i >> 4, cix = i & 15;
            sB[r][cix] = xr[r * XDBL + 16 + cix];
        }
    }

    float a[SSTATE];
    {
        const float* al = A_log + ((long)si * DINNER + d) * SSTATE;
        #pragma unroll
        for (int s = 0; s < SSTATE; s++) a[s] = -__expf(al[s]);
    }
    __syncthreads();

    const float* dtp = g_dt + ((long)sb * SEQ + n0) * DINNER + d;
    const float* xap = g_xa + ((long)sb * SEQ + n0) * DINNER + d;

    float h[SSTATE];
    #pragma unroll
    for (int s = 0; s < SSTATE; s++) h[s] = 0.f;
    float sdt = 0.f;

    #pragma unroll 4
    for (int nl = 0; nl < TCH; nl++) {
        float dtv = dtp[(long)nl * DINNER];
        float xav = xap[(long)nl * DINNER];
        float du = dtv * xav;
        sdt += dtv;
        #pragma unroll
        for (int s = 0; s < SSTATE; s++)
            h[s] = fmaf(__expf(dtv * a[s]), h[s], du * sB[nl][s]);
    }

    long off = ((long)chunk * (NSB * DINNER) + (long)sb * DINNER + d) * SSTATE;
    #pragma unroll
    for (int q = 0; q < 4; q++) {
        float4 P, L;
        P.x = __expf(a[q*4+0] * sdt); P.y = __expf(a[q*4+1] * sdt);
        P.z = __expf(a[q*4+2] * sdt); P.w = __expf(a[q*4+3] * sdt);
        L.x = h[q*4+0]; L.y = h[q*4+1]; L.z = h[q*4+2]; L.w = h[q*4+3];
        *(float4*)(g_P + off + q * 4) = P;
        *(float4*)(g_L + off + q * 4) = L;
    }
}

// ---------------- scan combine: sequential over chunks ----------------
__global__ void combine_kernel() {
    int idx = blockIdx.x * blockDim.x + threadIdx.x;   // 6*512*16 = 49152
    const int STR = NSB * DINNER * SSTATE;
    float H = 0.f;
    #pragma unroll
    for (int c = 0; c < NC; c++) {
        long o = (long)c * STR + idx;
        g_H[o] = H;
        H = fmaf(g_P[o], H, g_L[o]);
    }
}

// ---------------- scan phase 2: rescan + emit y ----------------
__global__ void __launch_bounds__(CHG)
scan2_kernel(const float* __restrict__ A_log, const float* __restrict__ Dp) {
    int chunk = blockIdx.x;
    int d = blockIdx.y * CHG + threadIdx.x;
    int sb = blockIdx.z;
    int si = sb / BDIM;
    int tid = threadIdx.x;
    int n0 = chunk * TCH;

    __shared__ float sBC[TCH][32];       // [.][0..15]=B  [.][16..31]=C
    {
        const float* xr = g_xdbl + ((long)sb * SEQ + n0) * XDBL;
        for (int i = tid; i < TCH * 32; i += CHG) {
            int r = i >> 5, cix = i & 31;
            sBC[r][cix] = xr[r * XDBL + 16 + cix];
        }
    }

    float a[SSTATE], h[SSTATE];
    {
        const float* al = A_log + ((long)si * DINNER + d) * SSTATE;
        #pragma unroll
        for (int s = 0; s < SSTATE; s++) a[s] = -__expf(al[s]);
        long off = ((long)chunk * (NSB * DINNER) + (long)sb * DINNER + d) * SSTATE;
        #pragma unroll
        for (int q = 0; q < 4; q++) {
            float4 v = *(const float4*)(g_H + off + q * 4);
            h[q*4+0] = v.x; h[q*4+1] = v.y; h[q*4+2] = v.z; h[q*4+3] = v.w;
        }
    }
    float Dpd = Dp[si * DINNER + d];
    __syncthreads();

    const float* dtp = g_dt + ((long)sb * SEQ + n0) * DINNER + d;
    const float* xap = g_xa + ((long)sb * SEQ + n0) * DINNER + d;
    const float* zzp = g_xz + ((long)sb * SEQ + n0) * (2 * DINNER) + DINNER + d;
    float* yo = g_y + ((long)sb * SEQ + n0) * DINNER + d;

    #pragma unroll 2
    for (int nl = 0; nl < TCH; nl++) {
        float dtv = dtp[(long)nl * DINNER];
        float xav = xap[(long)nl * DINNER];
        float zv  = zzp[(long)nl * (2 * DINNER)];
        float du = dtv * xav;
        float acc = 0.f;
        #pragma unroll
        for (int s = 0; s < SSTATE; s++) {
            h[s] = fmaf(__expf(dtv * a[s]), h[s], du * sBC[nl][s]);
            acc = fmaf(h[s], sBC[nl][16 + s], acc);
        }
        float sz = zv / (1.f + __expf(-zv));
        yo[(long)nl * DINNER] = (acc + xav * Dpd) * sz;
    }
}

// ---------------- mean pool (two stages) ----------------
__global__ void pool1_kernel() {
    int c = blockIdx.x;
    int b = blockIdx.y;
    int j = threadIdx.x;
    const float* base = g_multi + ((long)b * SEQ + c * (SEQ / NC)) * 768 + j;
    float s = 0.f;
    #pragma unroll 4
    for (int n = 0; n < SEQ / NC; n++) s += base[(long)n * 768];
    g_poolpart[((long)b * NC + c) * 768 + j] = s;
}
__global__ void pool2_kernel() {
    int b = blockIdx.x;
    int j = threadIdx.x;
    float s = 0.f;
    #pragma unroll
    for (int c = 0; c < NC; c++) s += g_poolpart[((long)b * NC + c) * 768 + j];
    g_pooled[b * 768 + j] = s * (1.f / SEQ);
}

// ---------------- aggregation coefficients ----------------
__global__ void coeffs_kernel(const float* __restrict__ w1, const float* __restrict__ b1,
                              const float* __restrict__ w2, const float* __restrict__ b2,
                              const float* __restrict__ temp) {
    int b = blockIdx.x;
    int d = threadIdx.x;
    const float* p = g_pooled + b * 768;
    const float* wr = w1 + (long)d * 768;
    float acc = b1[d];
    for (int e = 0; e < 768; e++) acc = fmaf(p[e], wr[e], acc);
    float x = acc;
    float cc = 0.7978845608028654f * (x + 0.044715f * x * x * x);
    float hg = 0.5f * x * (1.f + tanhf(cc));

    __shared__ float red[256];
    float logits[3];
    for (int k = 0; k < 3; k++) {
        red[d] = hg * w2[k * 256 + d];
        __syncthreads();
        for (int o = 128; o; o >>= 1) {
            if (d < o) red[d] += red[d + o];
            __syncthreads();
        }
        logits[k] = red[0] + b2[k];
        __syncthreads();
    }
    if (d == 0) {
        float m = fmaxf(logits[0], fmaxf(logits[1], logits[2]));
        float e0 = expf(logits[0] - m), e1 = expf(logits[1] - m), e2 = expf(logits[2] - m);
        float s = e0 + e1 + e2; e0 /= s; e1 /= s; e2 /= s;
        float invt = 1.f / (temp[0] + 1e-6f);
        float mm = fmaxf(e0, fmaxf(e1, e2)) * invt;
        float f0 = expf(e0 * invt - mm), f1 = expf(e1 * invt - mm), f2 = expf(e2 * invt - mm);
        float ss = f0 + f1 + f2;
        g_coeffs[b * 3 + 0] = f0 / ss;
        g_coeffs[b * 3 + 1] = f1 / ss;
        g_coeffs[b * 3 + 2] = f2 / ss;
    }
}

// ---------------- launch ----------------
extern "C" void kernel_launch(void* const* d_in, const int* in_sizes, int n_in,
                              void* d_out, int out_size) {
    const float* edge    = (const float*)d_in[0];
    const float* blob    = (const float*)d_in[1];
    const float* spec    = (const float*)d_in[2];
    const float* norm_w  = (const float*)d_in[3];
    const float* norm_b  = (const float*)d_in[4];
    const float* in_w    = (const float*)d_in[5];
    const float* conv_w  = (const float*)d_in[6];
    const float* conv_b  = (const float*)d_in[7];
    const float* xproj_w = (const float*)d_in[8];
    const float* dt_w    = (const float*)d_in[9];
    const float* dt_b    = (const float*)d_in[10];
    const float* A_log   = (const float*)d_in[11];
    const float* Dp      = (const float*)d_in[12];
    const float* out_w   = (const float*)d_in[13];
    const float* temp    = (const float*)d_in[14];
    const float* agg_w1  = (const float*)d_in[15];
    const float* agg_b1  = (const float*)d_in[16];
    const float* agg_w2  = (const float*)d_in[17];
    const float* agg_b2  = (const float*)d_in[18];
    const float* proj_w  = (const float*)d_in[19];
    const float* proj_b  = (const float*)d_in[20];
    float* out = (float*)d_out;

    float *xn, *xz, *xa, *xdbl, *dtb, *yb, *multi, *coef;
    cudaGetSymbolAddress((void**)&xn,    g_xn);
    cudaGetSymbolAddress((void**)&xz,    g_xz);
    cudaGetSymbolAddress((void**)&xa,    g_xa);
    cudaGetSymbolAddress((void**)&xdbl,  g_xdbl);
    cudaGetSymbolAddress((void**)&dtb,   g_dt);
    cudaGetSymbolAddress((void**)&yb,    g_y);
    cudaGetSymbolAddress((void**)&multi, g_multi);
    cudaGetSymbolAddress((void**)&coef,  g_coeffs);

    PtrTriple tri;  tri.p[0] = edge; tri.p[1] = blob; tri.p[2] = spec;
    PtrTriple tri0; tri0.p[0] = nullptr; tri0.p[1] = nullptr; tri0.p[2] = nullptr;
    PtrTriple triM; triM.p[0] = multi; triM.p[1] = nullptr; triM.p[2] = nullptr;

    const int SM128 = 2 * (128*32*4 + 128*32*4) + 64;   // 65600
    const int SM64  = 2 * (128*32*4 +  64*32*4) + 64;   // 49216
    cudaFuncSetAttribute(tgemm<128,0,false>, cudaFuncAttributeMaxDynamicSharedMemorySize, SM128);
    cudaFuncSetAttribute(tgemm<64, 0,true >, cudaFuncAttributeMaxDynamicSharedMemorySize, SM64);
    cudaFuncSetAttribute(tgemm<128,1,true >, cudaFuncAttributeMaxDynamicSharedMemorySize, SM128);
    cudaFuncSetAttribute(tgemm<128,2,false>, cudaFuncAttributeMaxDynamicSharedMemorySize, SM128);
    cudaFuncSetAttribute(tgemm<128,3,false>, cudaFuncAttributeMaxDynamicSharedMemorySize, SM128);

    // 1) layernorm
    layernorm_kernel<<<NSTREAM * NROWS, 256>>>(tri, norm_w, norm_b);

    // 2) in_proj (M=4096, N=1024, K=256 per stream)
    tgemm<128,0,false><<<dim3(8, 32, 3), 256, SM128>>>(
        xn, (long)NROWS*DMODEL, DMODEL,
        in_w, (long)1024*DMODEL, DMODEL,
        xz, (long)NROWS*1024, 1024, 0,
        1024, DMODEL, nullptr, 0, tri0, 0, nullptr);

    // 3) conv + silu
    conv_silu_kernel<<<(NSTREAM*NROWS*DINNER)/256, 256>>>(conv_w, conv_b);

    // 4) xproj (M=4096, N=48, K=512)
    tgemm<64,0,true><<<dim3(1, 32, 3), 256, SM64>>>(
        xa, (long)NROWS*DINNER, DINNER,
        xproj_w, (long)XDBL*DINNER, DINNER,
        xdbl, (long)NROWS*XDBL, XDBL, 0,
        XDBL, DINNER, nullptr, 0, tri0, 0, nullptr);

    // 5) dt = softplus(x_dbl[:, :16] @ dt_w^T + dt_b) (M=4096, N=512, K=16)
    tgemm<128,1,true><<<dim3(4, 32, 3), 256, SM128>>>(
        xdbl, (long)NROWS*XDBL, XDBL,
        dt_w, (long)DINNER*16, 16,
        dtb, (long)NROWS*DINNER, DINNER, 0,
        DINNER, 16, dt_b, DINNER, tri0, 0, nullptr);

    // 6) chunked selective scan: phase1 / combine / phase2
    scan1_kernel<<<dim3(NC, DINNER/CHG, NSB), CHG>>>(A_log);
    combine_kernel<<<(NSB*DINNER*SSTATE)/256, 256>>>();
    scan2_kernel<<<dim3(NC, DINNER/CHG, NSB), CHG>>>(A_log, Dp);

    // 7) out_proj + residual into concat layout multi (B,N,768)
    tgemm<128,2,false><<<dim3(2, 32, 3), 256, SM128>>>(
        yb, (long)NROWS*DINNER, DINNER,
        out_w, (long)DMODEL*DINNER, DINNER,
        multi, 0, 3*DMODEL, DMODEL,
        DMODEL, DINNER, nullptr, 0, tri, DMODEL, nullptr);

    // 8) mean pool
    pool1_kernel<<<dim3(NC, BDIM), 768>>>();
    pool2_kernel<<<BDIM, 768>>>();

    // 9) coefficients
    coeffs_kernel<<<BDIM, 256>>>(agg_w1, agg_b1, agg_w2, agg_b2, temp);

    // 10) final projection + weighted streams
    tgemm<128,3,false><<<dim3(2, 32, 1), 256, SM128>>>(
        multi, 0, 3*DMODEL,
        proj_w, 0, 3*DMODEL,
        out, 0, DMODEL, 0,
        DMODEL, 3*DMODEL, proj_b, 0, triM, 3*DMODEL, coef);
}